// round 12
// baseline (speedup 1.0000x reference)
#include <cuda_runtime.h>
#include <cuda_fp16.h>
#include <math.h>
#include <stdint.h>

#define BB 16
#define NN 4096
#define BN (BB*NN)
#define NIN 128
#define NODE_IN 256
#define HIDF 256
#define HIDA 128
#define OUTN 128
#define NH 4
#define NTOT 384
#define KTOT 256
#define TM 64
#define THREADS 256
#define NCH 64

#define XSTRH 272            // fp16 units; 544B row -> conflict-free LDS.64
#define WSTRB 96             // L1 weight tile row bytes (k-width 32)
#define W2STRB 160           // L2 weight tile row bytes (k-width 64, 128B data + 32 pad)
#define XBYTES (TM*XSTRH*2)  // 34816
#define WOFF   XBYTES
#define WBUFB  (NTOT*WSTRB)  // 36864 bytes per buffer (L2 tile 20480 fits inside)
#define LAOFF  (WOFF + 2*WBUFB)           // 108544
#define SMEM_BYTES (LAOFF + TM*8*4)       // 110592 -> 2 CTAs/SM

// ---------------- device scratch (no allocation allowed) ----------------
__device__ __half g_w1h[NTOT * KTOT];    // [n][k], k interleaved per 16-group
__device__ __half g_w2h[OUTN * KTOT];    // [n][k], same interleave
__device__ float  g_c1[BB * NTOT];       // per-batch context bias (exact fp32)
__device__ float  g_logits[(size_t)BN * NH];
__device__ float  g_stats[BB * NH * 2];
__device__ float  g_part[NCH * BB * OUTN];

// ---------------- helpers ----------------
__device__ __forceinline__ uint32_t smem_u32(const void* p) {
    uint32_t a;
    asm("{ .reg .u64 t; cvta.to.shared.u64 t, %1; cvt.u32.u64 %0, t; }" : "=r"(a) : "l"(p));
    return a;
}
__device__ __forceinline__ void cp16(uint32_t dst, const void* src) {
    asm volatile("cp.async.cg.shared.global [%0], [%1], 16;" :: "r"(dst), "l"(src));
}
#define CP_COMMIT() asm volatile("cp.async.commit_group;" ::: "memory")
#define CP_WAIT(n)  asm volatile("cp.async.wait_group %0;" :: "n"(n) : "memory")

__device__ __forceinline__ void mma_f16(float c[4],
                                        unsigned a0, unsigned a1, unsigned a2, unsigned a3,
                                        unsigned b0, unsigned b1) {
    asm volatile(
        "mma.sync.aligned.m16n8k16.row.col.f32.f16.f16.f32 "
        "{%0,%1,%2,%3}, {%4,%5,%6,%7}, {%8,%9}, {%0,%1,%2,%3};\n"
        : "+f"(c[0]), "+f"(c[1]), "+f"(c[2]), "+f"(c[3])
        : "r"(a0), "r"(a1), "r"(a2), "r"(a3), "r"(b0), "r"(b1));
}

// within-k16 interleave: k -> position, so (2t,2t+1,2t+8,2t+9) are contiguous
__device__ __forceinline__ int perm16(int k) {
    return ((k & 7) >> 1) * 4 + ((k >> 3) & 1) * 2 + (k & 1);
}
__device__ __forceinline__ int kpos(int k) {
    return (k >> 4) * 16 + perm16(k);
}
__device__ __forceinline__ int inv16(int p) {
    return (((p >> 1) & 1) << 3) + ((p >> 2) << 1) + (p & 1);
}

__device__ __forceinline__ int mask_mode(const void* mask) {
    unsigned w = *(const unsigned*)mask;      // mask[0,0] is always true (prefix mask)
    if (w == 1u) return 0;                    // int32
    if (w == 0x3f800000u) return 1;           // float32
    return 2;                                 // uint8 / bool
}
__device__ __forceinline__ bool mask_at(const void* mask, int idx, int mode) {
    if (mode == 0) return ((const int*)mask)[idx] != 0;
    if (mode == 1) return ((const float*)mask)[idx] != 0.0f;
    return ((const unsigned char*)mask)[idx] != 0;
}

// ---------------- prep: fp16 weights (interleaved) + context bias ----------------
__global__ void nb_prep_kernel(const float* __restrict__ fw1, const float* __restrict__ aw1,
                               const float* __restrict__ fw2,
                               const float* __restrict__ globs, const float* __restrict__ ctxt) {
    int idx = blockIdx.x * 256 + threadIdx.x;
    if (idx < NTOT * KTOT) {
        int n = idx >> 8, pp = idx & 255;
        int k = (pp & ~15) + inv16(pp & 15);
        float v = (n < HIDF) ? fw1[k * HIDF + n] : aw1[k * HIDA + (n - HIDF)];
        g_w1h[idx] = __float2half_rn(v);
    } else if (idx < NTOT * KTOT + OUTN * KTOT) {
        int j = idx - NTOT * KTOT;
        int n = j >> 8, pp = j & 255;
        int k = (pp & ~15) + inv16(pp & 15);
        g_w2h[j] = __float2half_rn(fw2[k * OUTN + n]);
    } else if (idx < NTOT * KTOT + OUTN * KTOT + BB * NTOT) {
        int j = idx - (NTOT * KTOT + OUTN * KTOT);
        int b = j / NTOT, n = j - b * NTOT;
        float s = 0.f;
        #pragma unroll 4
        for (int t = 0; t < 128; t++) {
            float hl = (t < 64) ? globs[b * 64 + t] : ctxt[b * 64 + (t - 64)];
            float w  = (n < HIDF) ? fw1[(NODE_IN + t) * HIDF + n]
                                  : aw1[(NODE_IN + t) * HIDA + (n - HIDF)];
            s += hl * w;
        }
        g_c1[j] = s;
    }
}

// ---------------- main fused kernel ----------------
extern __shared__ __align__(16) char smem_raw[];

__global__ void __launch_bounds__(THREADS, 2) nb_main_kernel(
    const float* __restrict__ nodes, const float* __restrict__ pooled_edges,
    const void* __restrict__ mask,
    const float* __restrict__ ln_g, const float* __restrict__ ln_b,
    const float* __restrict__ fb1, const float* __restrict__ ab1,
    const float* __restrict__ aw2, const float* __restrict__ ab2,
    const float* __restrict__ fb2,
    float* __restrict__ out)
{
    __half* xh    = (__half*)smem_raw;                  // [64][272] fp16 (h aliases)
    float* la_buf = (float*)(smem_raw + LAOFF);         // [64][8] logits partials

    const int tid  = threadIdx.x;
    const int lane = tid & 31;
    const int wid  = tid >> 5;
    const int b  = blockIdx.x >> 6;            // 64 CTAs per batch
    const int n0 = (blockIdx.x & 63) * TM;

    const int mode = mask_mode(mask);

    // ---- prefix-mask fast path: whole tile invalid -> new_nodes = nodes, logits=-inf
    if (!mask_at(mask, b * NN + n0, mode)) {
        const float4* src = (const float4*)(nodes + (size_t)(b * NN + n0) * OUTN);
        float4* dst = (float4*)(out + (size_t)(b * NN + n0) * OUTN);
        #pragma unroll
        for (int p = 0; p < 8; p++)
            dst[tid + p * THREADS] = src[tid + p * THREADS];
        int m = tid >> 2, h = tid & 3;
        g_logits[((size_t)b * NN + n0 + m) * NH + h] = -INFINITY;
        return;
    }

    const uint32_t wbase_a = smem_u32(smem_raw + WOFF);

    // prefetch L1 weight tile 0: 384 rows x 64B = 1536 chunks (6/thread)
    {
        #pragma unroll
        for (int p = 0; p < 6; p++) {
            int q = tid + p * 256;
            int row = q >> 2, c = q & 3;
            cp16(wbase_a + row * WSTRB + c * 16,
                 (const char*)g_w1h + (size_t)row * KTOT * 2 + c * 16);
        }
        CP_COMMIT();
    }

    // -------- Phase 0: LayerNorm -> X (fp16, k-interleaved), vectorized --------
    for (int m = wid; m < TM; m += 8) {
        const float4* np4 = (const float4*)(nodes + (size_t)(b * NN + n0 + m) * NIN);
        const float4* pp4 = (const float4*)(pooled_edges + (size_t)(b * NN + n0 + m) * NIN);
        float4 va = np4[lane];
        float4 vb = pp4[lane];
        float s  = va.x + va.y + va.z + va.w + vb.x + vb.y + vb.z + vb.w;
        float sq = va.x*va.x + va.y*va.y + va.z*va.z + va.w*va.w
                 + vb.x*vb.x + vb.y*vb.y + vb.z*vb.z + vb.w*vb.w;
        #pragma unroll
        for (int o = 16; o; o >>= 1) {
            s  += __shfl_xor_sync(0xffffffffu, s, o);
            sq += __shfl_xor_sync(0xffffffffu, sq, o);
        }
        float mu  = s * (1.0f / NODE_IN);
        float var = sq * (1.0f / NODE_IN) - mu * mu;
        float rs  = rsqrtf(var + 1e-5f);
        int ja = lane * 4;
        int jb = 128 + lane * 4;
        float a0 = (va.x - mu) * rs * ln_g[ja]     + ln_b[ja];
        float a1 = (va.y - mu) * rs * ln_g[ja + 1] + ln_b[ja + 1];
        float a2 = (va.z - mu) * rs * ln_g[ja + 2] + ln_b[ja + 2];
        float a3 = (va.w - mu) * rs * ln_g[ja + 3] + ln_b[ja + 3];
        float b0 = (vb.x - mu) * rs * ln_g[jb]     + ln_b[jb];
        float b1 = (vb.y - mu) * rs * ln_g[jb + 1] + ln_b[jb + 1];
        float b2 = (vb.z - mu) * rs * ln_g[jb + 2] + ln_b[jb + 2];
        float b3 = (vb.w - mu) * rs * ln_g[jb + 3] + ln_b[jb + 3];
        __half* xr = xh + m * XSTRH;
        *(__half2*)(xr + kpos(ja))     = __floats2half2_rn(a0, a1);
        *(__half2*)(xr + kpos(ja + 2)) = __floats2half2_rn(a2, a3);
        *(__half2*)(xr + kpos(jb))     = __floats2half2_rn(b0, b1);
        *(__half2*)(xr + kpos(jb + 2)) = __floats2half2_rn(b2, b3);
    }

    const int wm = wid >> 2;   // 0..1 (M)
    const int wn = wid & 3;    // 0..3 (N)
    const int tq = lane & 3;
    const int gg = lane >> 2;

    // -------- Layer 1: C1[64x384] = X @ W1  (8 k-tiles of 32, single-sync pipeline)
    float acc[2][12][4];
    #pragma unroll
    for (int i = 0; i < 2; i++)
        #pragma unroll
        for (int j = 0; j < 12; j++)
            #pragma unroll
            for (int e = 0; e < 4; e++) acc[i][j][e] = 0.f;

    #pragma unroll 1
    for (int kt = 0; kt < 8; kt++) {
        CP_WAIT(0);
        __syncthreads();   // tile kt ready; all warps done reading buf (kt+1)&1
        if (kt + 1 < 8) {
            uint32_t base = wbase_a + ((kt + 1) & 1) * WBUFB;
            #pragma unroll
            for (int p = 0; p < 6; p++) {
                int q = tid + p * 256;
                int row = q >> 2, c = q & 3;
                cp16(base + row * WSTRB + c * 16,
                     (const char*)g_w1h + (size_t)row * KTOT * 2 + (kt + 1) * 64 + c * 16);
            }
            CP_COMMIT();
        }
        const char* xb = smem_raw;
        const char* wb = smem_raw + WOFF + (kt & 1) * WBUFB;
        #pragma unroll
        for (int s = 0; s < 2; s++) {
            int koff = (kt * 2 + s) * 32 + tq * 8;
            uint2 aL[2], aH[2];
            #pragma unroll
            for (int i = 0; i < 2; i++) {
                int rm = wm * 32 + i * 16 + gg;
                aL[i] = *(const uint2*)(xb + rm * (XSTRH * 2) + koff);
                aH[i] = *(const uint2*)(xb + (rm + 8) * (XSTRH * 2) + koff);
            }
            #pragma unroll
            for (int j = 0; j < 12; j++) {
                int n = wn * 96 + j * 8 + gg;
                uint2 bb = *(const uint2*)(wb + n * WSTRB + s * 32 + tq * 8);
                mma_f16(acc[0][j], aL[0].x, aH[0].x, aL[0].y, aH[0].y, bb.x, bb.y);
                mma_f16(acc[1][j], aL[1].x, aH[1].x, aL[1].y, aH[1].y, bb.x, bb.y);
            }
        }
    }
    __syncthreads();   // all L1 reads of X done before epilogue-1 overwrites h into it

    // prefetch L2 weight tile 0 (k-width 64): 128 rows x 128B = 1024 chunks (4/thread)
    {
        #pragma unroll
        for (int p = 0; p < 4; p++) {
            int q = tid + p * 256;
            int row = q >> 3, c = q & 7;
            cp16(wbase_a + row * W2STRB + c * 16,
                 (const char*)g_w2h + (size_t)row * KTOT * 2 + c * 16);
        }
        CP_COMMIT();
    }

    // -------- epilogue 1: bias + ctx + lrelu; feat -> h (fp16); attn -> la partials
    const float* c1b = g_c1 + b * NTOT;
    const float4* aw2v = (const float4*)aw2;   // [128] rows of 4 heads
    float la[2][2][4];
    #pragma unroll
    for (int i = 0; i < 2; i++)
        #pragma unroll
        for (int eh = 0; eh < 2; eh++)
            #pragma unroll
            for (int h = 0; h < 4; h++) la[i][eh][h] = 0.f;

    #pragma unroll
    for (int i = 0; i < 2; i++) {
        #pragma unroll
        for (int j = 0; j < 12; j++) {
            int nb = wn * 96 + j * 8 + 2 * tq;
            if (nb < HIDF) {
                #pragma unroll
                for (int eh = 0; eh < 2; eh++) {
                    int m = wm * 32 + i * 16 + gg + eh * 8;
                    float v0 = acc[i][j][eh * 2]     + c1b[nb]     + fb1[nb];
                    float v1 = acc[i][j][eh * 2 + 1] + c1b[nb + 1] + fb1[nb + 1];
                    v0 = (v0 > 0.f) ? v0 : 0.01f * v0;
                    v1 = (v1 > 0.f) ? v1 : 0.01f * v1;
                    *(__half2*)(xh + m * XSTRH + kpos(nb)) = __floats2half2_rn(v0, v1);
                }
            } else {
                int ka = nb - HIDF;
                float4 w0 = aw2v[ka];
                float4 w1 = aw2v[ka + 1];
                #pragma unroll
                for (int eh = 0; eh < 2; eh++) {
                    float v0 = acc[i][j][eh * 2]     + c1b[nb]     + ab1[ka];
                    float v1 = acc[i][j][eh * 2 + 1] + c1b[nb + 1] + ab1[ka + 1];
                    v0 = (v0 > 0.f) ? v0 : 0.01f * v0;
                    v1 = (v1 > 0.f) ? v1 : 0.01f * v1;
                    la[i][eh][0] += v0 * w0.x + v1 * w1.x;
                    la[i][eh][1] += v0 * w0.y + v1 * w1.y;
                    la[i][eh][2] += v0 * w0.z + v1 * w1.z;
                    la[i][eh][3] += v0 * w0.w + v1 * w1.w;
                }
            }
        }
    }

    // reduce attn partials over the 4 tq lanes, stash in la_buf
    if (wn >= 2) {
        #pragma unroll
        for (int i = 0; i < 2; i++)
            #pragma unroll
            for (int eh = 0; eh < 2; eh++)
                #pragma unroll
                for (int h = 0; h < 4; h++) {
                    float v = la[i][eh][h];
                    v += __shfl_xor_sync(0xffffffffu, v, 1);
                    v += __shfl_xor_sync(0xffffffffu, v, 2);
                    la[i][eh][h] = v;
                }
        if (tq == 0) {
            #pragma unroll
            for (int i = 0; i < 2; i++)
                #pragma unroll
                for (int eh = 0; eh < 2; eh++) {
                    int m = wm * 32 + i * 16 + gg + eh * 8;
                    #pragma unroll
                    for (int h = 0; h < 4; h++)
                        la_buf[m * 8 + (wn - 2) * 4 + h] = la[i][eh][h];
                }
        }
    }

    // -------- Layer 2: C2[64x128] = h @ W2  (4 k-tiles of 64, single-sync pipeline)
    float acc2[2][4][4];
    #pragma unroll
    for (int i = 0; i < 2; i++)
        #pragma unroll
        for (int j = 0; j < 4; j++)
            #pragma unroll
            for (int e = 0; e < 4; e++) acc2[i][j][e] = 0.f;

    #pragma unroll 1
    for (int kt = 0; kt < 4; kt++) {
        CP_WAIT(0);
        __syncthreads();   // tile kt ready; first iter also publishes h / la_buf writes
        if (kt + 1 < 4) {
            uint32_t base = wbase_a + ((kt + 1) & 1) * WBUFB;
            #pragma unroll
            for (int p = 0; p < 4; p++) {
                int q = tid + p * 256;
                int row = q >> 3, c = q & 7;
                cp16(base + row * W2STRB + c * 16,
                     (const char*)g_w2h + (size_t)row * KTOT * 2 + (kt + 1) * 128 + c * 16);
            }
            CP_COMMIT();
        }
        const char* xb = smem_raw;
        const char* wb = smem_raw + WOFF + (kt & 1) * WBUFB;
        #pragma unroll
        for (int s = 0; s < 4; s++) {
            int koff = kt * 128 + s * 32 + tq * 8;
            uint2 aL[2], aH[2];
            #pragma unroll
            for (int i = 0; i < 2; i++) {
                int rm = wm * 32 + i * 16 + gg;
                aL[i] = *(const uint2*)(xb + rm * (XSTRH * 2) + koff);
                aH[i] = *(const uint2*)(xb + (rm + 8) * (XSTRH * 2) + koff);
            }
            #pragma unroll
            for (int j = 0; j < 4; j++) {
                int n = wn * 32 + j * 8 + gg;
                uint2 bb = *(const uint2*)(wb + n * W2STRB + s * 32 + tq * 8);
                mma_f16(acc2[0][j], aL[0].x, aH[0].x, aL[0].y, aH[0].y, bb.x, bb.y);
                mma_f16(acc2[1][j], aL[1].x, aH[1].x, aL[1].y, aH[1].y, bb.x, bb.y);
            }
        }
    }

    // -------- epilogue 2: bias, mask, residual, store new_nodes --------
    #pragma unroll
    for (int i = 0; i < 2; i++) {
        #pragma unroll
        for (int j = 0; j < 4; j++) {
            #pragma unroll
            for (int e = 0; e < 4; e += 2) {
                int m = wm * 32 + i * 16 + gg + ((e >> 1) * 8);
                int n = wn * 32 + j * 8 + 2 * tq;
                int nd = n0 + m;
                bool valid = mask_at(mask, b * NN + nd, mode);
                size_t base = ((size_t)b * NN + nd) * OUTN + n;
                float v0 = acc2[i][j][e] + fb2[n];
                float v1 = acc2[i][j][e + 1] + fb2[n + 1];
                out[base]     = (valid ? v0 : 0.f) + nodes[base];
                out[base + 1] = (valid ? v1 : 0.f) + nodes[base + 1];
            }
        }
    }

    // -------- logits: combine the two warp-halves from la_buf --------
    {
        int m = tid >> 2, h = tid & 3;
        float a4 = la_buf[m * 8 + h] + la_buf[m * 8 + 4 + h] + ab2[h];
        int n = n0 + m;
        bool valid = mask_at(mask, b * NN + n, mode);
        g_logits[((size_t)b * NN + n) * NH + h] = valid ? a4 : -INFINITY;
    }
}

// ---------------- softmax stats: one block per batch, float4 over 4 heads ----------
__global__ void nb_softmax_stats_kernel() {
    __shared__ float4 red4[256];
    int b = blockIdx.x;
    int tid = threadIdx.x;
    const float4* lp = (const float4*)(g_logits + (size_t)b * NN * NH);
    float4 mx = make_float4(-INFINITY, -INFINITY, -INFINITY, -INFINITY);
    #pragma unroll 4
    for (int t = 0; t < NN / 256; t++) {
        float4 l = lp[t * 256 + tid];
        mx.x = fmaxf(mx.x, l.x); mx.y = fmaxf(mx.y, l.y);
        mx.z = fmaxf(mx.z, l.z); mx.w = fmaxf(mx.w, l.w);
    }
    red4[tid] = mx;
    __syncthreads();
    for (int o = 128; o; o >>= 1) {
        if (tid < o) {
            float4 a = red4[tid], c = red4[tid + o];
            a.x = fmaxf(a.x, c.x); a.y = fmaxf(a.y, c.y);
            a.z = fmaxf(a.z, c.z); a.w = fmaxf(a.w, c.w);
            red4[tid] = a;
        }
        __syncthreads();
    }
    float4 gm = red4[0];
    __syncthreads();
    float4 sm = make_float4(0.f, 0.f, 0.f, 0.f);
    #pragma unroll 4
    for (int t = 0; t < NN / 256; t++) {
        float4 l = lp[t * 256 + tid];
        sm.x += expf(l.x - gm.x); sm.y += expf(l.y - gm.y);
        sm.z += expf(l.z - gm.z); sm.w += expf(l.w - gm.w);
    }
    red4[tid] = sm;
    __syncthreads();
    for (int o = 128; o; o >>= 1) {
        if (tid < o) {
            float4 a = red4[tid], c = red4[tid + o];
            a.x += c.x; a.y += c.y; a.z += c.z; a.w += c.w;
            red4[tid] = a;
        }
        __syncthreads();
    }
    if (tid < 4) {
        float4 gs = red4[0];
        float gmv = (tid == 0) ? gm.x : (tid == 1) ? gm.y : (tid == 2) ? gm.z : gm.w;
        float gsv = (tid == 0) ? gs.x : (tid == 1) ? gs.y : (tid == 2) ? gs.z : gs.w;
        g_stats[(b * NH + tid) * 2]     = gmv;
        g_stats[(b * NH + tid) * 2 + 1] = gsv;
    }
}

// ---------------- deterministic two-stage pooled reduction (NCH=64) ----------------
__global__ void nb_pooled_partial_kernel(const float* __restrict__ newnodes) {
    __shared__ float sd[8][OUTN + 4];
    int b  = blockIdx.x;
    int ch = blockIdx.y;
    int q  = threadIdx.x & 31;
    int ro = threadIdx.x >> 5;
    int c4 = q * 4;
    int h  = q >> 3;
    float gmax = g_stats[(b * NH + h) * 2];
    float gsum = g_stats[(b * NH + h) * 2 + 1];
    float scale = 0.08838834764831845f / gsum;   // 1/sqrt(128)/sum
    float ax = 0.f, ay = 0.f, az = 0.f, aw = 0.f;
    int nbase = ch * (NN / NCH);
    #pragma unroll
    for (int r = ro; r < NN / NCH; r += 8) {
        int n = nbase + r;
        float l = g_logits[((size_t)b * NN + n) * NH + h];
        float w = expf(l - gmax) * scale;        // masked: l=-inf -> w=0
        float4 v = *(const float4*)&newnodes[((size_t)b * NN + n) * OUTN + c4];
        ax += v.x * w; ay += v.y * w; az += v.z * w; aw += v.w * w;
    }
    sd[ro][c4]     = ax;
    sd[ro][c4 + 1] = ay;
    sd[ro][c4 + 2] = az;
    sd[ro][c4 + 3] = aw;
    __syncthreads();
    if (threadIdx.x < OUTN) {
        float s = 0.f;
        #pragma unroll
        for (int r = 0; r < 8; r++) s += sd[r][threadIdx.x];
        g_part[(ch * BB + b) * OUTN + threadIdx.x] = s;
    }
}

__global__ void nb_pooled_final_kernel(float* __restrict__ out) {
    int idx = blockIdx.x * 256 + threadIdx.x;
    float s = 0.f;
    #pragma unroll 8
    for (int ch = 0; ch < NCH; ch++) s += g_part[ch * BB * OUTN + idx];
    out[(size_t)BN * OUTN + idx] = s;
}

extern "C" void kernel_launch(void* const* d_in, const int* in_sizes, int n_in,
                              void* d_out, int out_size) {
    const float* nodes        = (const float*)d_in[0];
    const float* pooled_edges = (const float*)d_in[1];
    const void*  mask         = d_in[2];
    const float* globs        = (const float*)d_in[3];
    const float* ctxt         = (const float*)d_in[4];
    const float* ln_g         = (const float*)d_in[5];
    const float* ln_b         = (const float*)d_in[6];
    const float* fw1          = (const float*)d_in[7];
    const float* fb1          = (const float*)d_in[8];
    const float* fw2          = (const float*)d_in[9];
    const float* fb2          = (const float*)d_in[10];
    const float* aw1          = (const float*)d_in[11];
    const float* ab1          = (const float*)d_in[12];
    const float* aw2          = (const float*)d_in[13];
    const float* ab2          = (const float*)d_in[14];
    float* out = (float*)d_out;

    int prep_elems = NTOT * KTOT + OUTN * KTOT + BB * NTOT;
    nb_prep_kernel<<<(prep_elems + 255) / 256, 256>>>(fw1, aw1, fw2, globs, ctxt);

    cudaFuncSetAttribute(nb_main_kernel,
                         cudaFuncAttributeMaxDynamicSharedMemorySize, SMEM_BYTES);
    nb_main_kernel<<<BB * (NN / TM), THREADS, SMEM_BYTES>>>(
        nodes, pooled_edges, mask, ln_g, ln_b,
        fb1, ab1, aw2, ab2, fb2, out);

    nb_softmax_stats_kernel<<<BB, 256>>>();

    dim3 pg(BB, NCH);
    nb_pooled_partial_kernel<<<pg, 256>>>(out);

    nb_pooled_final_kernel<<<(BB * OUTN) / 256, 256>>>(out);
}

// round 13
// speedup vs baseline: 1.1031x; 1.1031x over previous
#include <cuda_runtime.h>
#include <cuda_fp16.h>
#include <math.h>
#include <stdint.h>

#define BB 16
#define NN 4096
#define BN (BB*NN)
#define NIN 128
#define NODE_IN 256
#define HIDF 256
#define HIDA 128
#define OUTN 128
#define NH 4
#define NTOT 384
#define KTOT 256
#define TM 64
#define THREADS 256
#define NCH 32

#define XSTRH 264            // fp16 units; 528B row = 33 x16B (odd) -> LDSM conflict-free
#define W1STRB 80            // L1 weight tile row bytes (64 data + 16 pad; 5 x16B odd)
#define W2STRB 144           // L2 weight tile row bytes (128 data + 16 pad; 9 x16B odd)
#define XBYTES (TM*XSTRH*2)  // 33792
#define WOFF   XBYTES
#define WBUFB  (NTOT*W1STRB) // 30720 per buffer (L2 tile 18432 fits)
#define LAOFF  (WOFF + 2*WBUFB)           // 95232
#define SMEM_BYTES (LAOFF + TM*8*4)       // 97280 -> 2 CTAs/SM

// ---------------- device scratch (no allocation allowed) ----------------
__device__ __half g_w1h[NTOT * KTOT];    // [n][k] plain row-major
__device__ __half g_w2h[OUTN * KTOT];    // [n][k] plain
__device__ float  g_c1[BB * NTOT];       // per-batch context bias (exact fp32)
__device__ float  g_logits[(size_t)BN * NH];
__device__ float  g_stats[BB * NH * 2];
__device__ float  g_part[NCH * BB * OUTN];

// ---------------- helpers ----------------
__device__ __forceinline__ uint32_t smem_u32(const void* p) {
    uint32_t a;
    asm("{ .reg .u64 t; cvta.to.shared.u64 t, %1; cvt.u32.u64 %0, t; }" : "=r"(a) : "l"(p));
    return a;
}
__device__ __forceinline__ void cp16(uint32_t dst, const void* src) {
    asm volatile("cp.async.cg.shared.global [%0], [%1], 16;" :: "r"(dst), "l"(src));
}
#define CP_COMMIT() asm volatile("cp.async.commit_group;" ::: "memory")
#define CP_WAIT(n)  asm volatile("cp.async.wait_group %0;" :: "n"(n) : "memory")

__device__ __forceinline__ void ldsm_x4(uint32_t& r0, uint32_t& r1, uint32_t& r2,
                                        uint32_t& r3, uint32_t addr) {
    asm volatile("ldmatrix.sync.aligned.m8n8.x4.shared.b16 {%0,%1,%2,%3}, [%4];"
                 : "=r"(r0), "=r"(r1), "=r"(r2), "=r"(r3) : "r"(addr));
}

__device__ __forceinline__ void mma_f16(float c[4],
                                        unsigned a0, unsigned a1, unsigned a2, unsigned a3,
                                        unsigned b0, unsigned b1) {
    asm volatile(
        "mma.sync.aligned.m16n8k16.row.col.f32.f16.f16.f32 "
        "{%0,%1,%2,%3}, {%4,%5,%6,%7}, {%8,%9}, {%0,%1,%2,%3};\n"
        : "+f"(c[0]), "+f"(c[1]), "+f"(c[2]), "+f"(c[3])
        : "r"(a0), "r"(a1), "r"(a2), "r"(a3), "r"(b0), "r"(b1));
}

__device__ __forceinline__ int mask_mode(const void* mask) {
    unsigned w = *(const unsigned*)mask;      // mask[0,0] is always true (prefix mask)
    if (w == 1u) return 0;                    // int32
    if (w == 0x3f800000u) return 1;           // float32
    return 2;                                 // uint8 / bool
}
__device__ __forceinline__ bool mask_at(const void* mask, int idx, int mode) {
    if (mode == 0) return ((const int*)mask)[idx] != 0;
    if (mode == 1) return ((const float*)mask)[idx] != 0.0f;
    return ((const unsigned char*)mask)[idx] != 0;
}

// ---------------- prep: fp16 weights (plain [n][k]) + context bias ----------------
__global__ void nb_prep_kernel(const float* __restrict__ fw1, const float* __restrict__ aw1,
                               const float* __restrict__ fw2,
                               const float* __restrict__ globs, const float* __restrict__ ctxt) {
    int idx = blockIdx.x * 256 + threadIdx.x;
    if (idx < NTOT * KTOT) {
        int n = idx >> 8, k = idx & 255;
        float v = (n < HIDF) ? fw1[k * HIDF + n] : aw1[k * HIDA + (n - HIDF)];
        g_w1h[idx] = __float2half_rn(v);
    } else if (idx < NTOT * KTOT + OUTN * KTOT) {
        int j = idx - NTOT * KTOT;
        int n = j >> 8, k = j & 255;
        g_w2h[j] = __float2half_rn(fw2[k * OUTN + n]);
    } else if (idx < NTOT * KTOT + OUTN * KTOT + BB * NTOT) {
        int j = idx - (NTOT * KTOT + OUTN * KTOT);
        int b = j / NTOT, n = j - b * NTOT;
        float s = 0.f;
        #pragma unroll 4
        for (int t = 0; t < 128; t++) {
            float hl = (t < 64) ? globs[b * 64 + t] : ctxt[b * 64 + (t - 64)];
            float w  = (n < HIDF) ? fw1[(NODE_IN + t) * HIDF + n]
                                  : aw1[(NODE_IN + t) * HIDA + (n - HIDF)];
            s += hl * w;
        }
        g_c1[j] = s;
    }
}

// ---------------- main fused kernel ----------------
extern __shared__ __align__(16) char smem_raw[];

__global__ void __launch_bounds__(THREADS, 2) nb_main_kernel(
    const float* __restrict__ nodes, const float* __restrict__ pooled_edges,
    const void* __restrict__ mask,
    const float* __restrict__ ln_g, const float* __restrict__ ln_b,
    const float* __restrict__ fb1, const float* __restrict__ ab1,
    const float* __restrict__ aw2, const float* __restrict__ ab2,
    const float* __restrict__ fb2,
    float* __restrict__ out)
{
    __half* xh    = (__half*)smem_raw;                  // [64][264] fp16 plain (h aliases)
    float* la_buf = (float*)(smem_raw + LAOFF);         // [64][8] logits partials

    const int tid  = threadIdx.x;
    const int lane = tid & 31;
    const int wid  = tid >> 5;
    const int b  = blockIdx.x >> 6;            // 64 CTAs per batch
    const int n0 = (blockIdx.x & 63) * TM;

    const int mode = mask_mode(mask);

    // ---- prefix-mask fast path: whole tile invalid -> new_nodes = nodes, logits=-inf
    if (!mask_at(mask, b * NN + n0, mode)) {
        const float4* src = (const float4*)(nodes + (size_t)(b * NN + n0) * OUTN);
        float4* dst = (float4*)(out + (size_t)(b * NN + n0) * OUTN);
        #pragma unroll
        for (int p = 0; p < 8; p++)
            dst[tid + p * THREADS] = src[tid + p * THREADS];
        int m = tid >> 2, h = tid & 3;
        g_logits[((size_t)b * NN + n0 + m) * NH + h] = -INFINITY;
        return;
    }

    const uint32_t xbase  = smem_u32(smem_raw);
    const uint32_t wbase0 = xbase + WOFF;

    // prefetch L1 weight tile 0: 384 rows x 64B = 1536 chunks (6/thread)
    {
        #pragma unroll
        for (int p = 0; p < 6; p++) {
            int q = tid + p * 256;
            int row = q >> 2, c = q & 3;
            cp16(wbase0 + row * W1STRB + c * 16,
                 (const char*)g_w1h + (size_t)row * KTOT * 2 + c * 16);
        }
        CP_COMMIT();
    }

    // -------- Phase 0: LayerNorm -> X (fp16 plain rows), vectorized --------
    for (int m = wid; m < TM; m += 8) {
        const float4* np4 = (const float4*)(nodes + (size_t)(b * NN + n0 + m) * NIN);
        const float4* pp4 = (const float4*)(pooled_edges + (size_t)(b * NN + n0 + m) * NIN);
        float4 va = np4[lane];
        float4 vb = pp4[lane];
        float s  = va.x + va.y + va.z + va.w + vb.x + vb.y + vb.z + vb.w;
        float sq = va.x*va.x + va.y*va.y + va.z*va.z + va.w*va.w
                 + vb.x*vb.x + vb.y*vb.y + vb.z*vb.z + vb.w*vb.w;
        #pragma unroll
        for (int o = 16; o; o >>= 1) {
            s  += __shfl_xor_sync(0xffffffffu, s, o);
            sq += __shfl_xor_sync(0xffffffffu, sq, o);
        }
        float mu  = s * (1.0f / NODE_IN);
        float var = sq * (1.0f / NODE_IN) - mu * mu;
        float rs  = rsqrtf(var + 1e-5f);
        int ja = lane * 4;
        int jb = 128 + lane * 4;
        float a0 = (va.x - mu) * rs * ln_g[ja]     + ln_b[ja];
        float a1 = (va.y - mu) * rs * ln_g[ja + 1] + ln_b[ja + 1];
        float a2 = (va.z - mu) * rs * ln_g[ja + 2] + ln_b[ja + 2];
        float a3 = (va.w - mu) * rs * ln_g[ja + 3] + ln_b[ja + 3];
        float b0 = (vb.x - mu) * rs * ln_g[jb]     + ln_b[jb];
        float b1 = (vb.y - mu) * rs * ln_g[jb + 1] + ln_b[jb + 1];
        float b2 = (vb.z - mu) * rs * ln_g[jb + 2] + ln_b[jb + 2];
        float b3 = (vb.w - mu) * rs * ln_g[jb + 3] + ln_b[jb + 3];
        __half* xr = xh + m * XSTRH;
        *(__half2*)(xr + ja)     = __floats2half2_rn(a0, a1);
        *(__half2*)(xr + ja + 2) = __floats2half2_rn(a2, a3);
        *(__half2*)(xr + jb)     = __floats2half2_rn(b0, b1);
        *(__half2*)(xr + jb + 2) = __floats2half2_rn(b2, b3);
    }

    const int wm = wid >> 2;   // 0..1 (M)
    const int wn = wid & 3;    // 0..3 (N)
    const int tq = lane & 3;
    const int gg = lane >> 2;

    // LDSM address lane-constants
    const int aRow  = (lane & 7) + ((lane >> 3) & 1) * 8;   // A: row extra from bit3
    const int aColH = ((lane >> 4) & 1) * 8;                // A: col extra from bit4
    const int bRow  = (lane & 7) + ((lane >> 4) & 1) * 8;   // B: row extra from bit4
    const int bColH = ((lane >> 3) & 1) * 8;                // B: col extra from bit3

    // -------- Layer 1: C1[64x384] = X @ W1  (8 k-tiles of 32, single-sync pipeline)
    float acc[2][12][4];
    #pragma unroll
    for (int i = 0; i < 2; i++)
        #pragma unroll
        for (int j = 0; j < 12; j++)
            #pragma unroll
            for (int e = 0; e < 4; e++) acc[i][j][e] = 0.f;

    #pragma unroll 1
    for (int kt = 0; kt < 8; kt++) {
        CP_WAIT(0);
        __syncthreads();   // tile kt ready; all warps done reading buf (kt+1)&1
        if (kt + 1 < 8) {
            uint32_t base = wbase0 + ((kt + 1) & 1) * WBUFB;
            #pragma unroll
            for (int p = 0; p < 6; p++) {
                int q = tid + p * 256;
                int row = q >> 2, c = q & 3;
                cp16(base + row * W1STRB + c * 16,
                     (const char*)g_w1h + (size_t)row * KTOT * 2 + (kt + 1) * 64 + c * 16);
            }
            CP_COMMIT();
        }
        uint32_t wb = wbase0 + (kt & 1) * WBUFB;
        #pragma unroll
        for (int s = 0; s < 2; s++) {
            uint32_t A0[4], A1[4];
            uint32_t xcol = (uint32_t)(kt * 32 + s * 16 + aColH) * 2;
            ldsm_x4(A0[0], A0[1], A0[2], A0[3],
                    xbase + (wm * 32 + aRow) * (XSTRH * 2) + xcol);
            ldsm_x4(A1[0], A1[1], A1[2], A1[3],
                    xbase + (wm * 32 + 16 + aRow) * (XSTRH * 2) + xcol);
            uint32_t wcol = (uint32_t)(s * 16 + bColH) * 2;
            #pragma unroll
            for (int jj = 0; jj < 6; jj++) {
                uint32_t r0, r1, r2, r3;
                ldsm_x4(r0, r1, r2, r3,
                        wb + (wn * 96 + jj * 16 + bRow) * W1STRB + wcol);
                mma_f16(acc[0][2*jj],   A0[0], A0[1], A0[2], A0[3], r0, r1);
                mma_f16(acc[1][2*jj],   A1[0], A1[1], A1[2], A1[3], r0, r1);
                mma_f16(acc[0][2*jj+1], A0[0], A0[1], A0[2], A0[3], r2, r3);
                mma_f16(acc[1][2*jj+1], A1[0], A1[1], A1[2], A1[3], r2, r3);
            }
        }
    }
    __syncthreads();   // all L1 reads of X done before epilogue-1 overwrites h into it

    // prefetch L2 weight tile 0 (k-width 64): 128 rows x 128B = 1024 chunks (4/thread)
    {
        #pragma unroll
        for (int p = 0; p < 4; p++) {
            int q = tid + p * 256;
            int row = q >> 3, c = q & 7;
            cp16(wbase0 + row * W2STRB + c * 16,
                 (const char*)g_w2h + (size_t)row * KTOT * 2 + c * 16);
        }
        CP_COMMIT();
    }

    // -------- epilogue 1: bias + ctx + lrelu; feat -> h (fp16 plain); attn -> la ----
    const float* c1b = g_c1 + b * NTOT;
    const float4* aw2v = (const float4*)aw2;   // [128] rows of 4 heads
    float la[2][2][4];
    #pragma unroll
    for (int i = 0; i < 2; i++)
        #pragma unroll
        for (int eh = 0; eh < 2; eh++)
            #pragma unroll
            for (int h = 0; h < 4; h++) la[i][eh][h] = 0.f;

    #pragma unroll
    for (int i = 0; i < 2; i++) {
        #pragma unroll
        for (int j = 0; j < 12; j++) {
            int nb = wn * 96 + j * 8 + 2 * tq;
            if (nb < HIDF) {
                #pragma unroll
                for (int eh = 0; eh < 2; eh++) {
                    int m = wm * 32 + i * 16 + gg + eh * 8;
                    float v0 = acc[i][j][eh * 2]     + c1b[nb]     + fb1[nb];
                    float v1 = acc[i][j][eh * 2 + 1] + c1b[nb + 1] + fb1[nb + 1];
                    v0 = (v0 > 0.f) ? v0 : 0.01f * v0;
                    v1 = (v1 > 0.f) ? v1 : 0.01f * v1;
                    *(__half2*)(xh + m * XSTRH + nb) = __floats2half2_rn(v0, v1);
                }
            } else {
                int ka = nb - HIDF;
                float4 w0 = aw2v[ka];
                float4 w1 = aw2v[ka + 1];
                #pragma unroll
                for (int eh = 0; eh < 2; eh++) {
                    float v0 = acc[i][j][eh * 2]     + c1b[nb]     + ab1[ka];
                    float v1 = acc[i][j][eh * 2 + 1] + c1b[nb + 1] + ab1[ka + 1];
                    v0 = (v0 > 0.f) ? v0 : 0.01f * v0;
                    v1 = (v1 > 0.f) ? v1 : 0.01f * v1;
                    la[i][eh][0] += v0 * w0.x + v1 * w1.x;
                    la[i][eh][1] += v0 * w0.y + v1 * w1.y;
                    la[i][eh][2] += v0 * w0.z + v1 * w1.z;
                    la[i][eh][3] += v0 * w0.w + v1 * w1.w;
                }
            }
        }
    }

    // reduce attn partials over the 4 tq lanes, stash in la_buf
    if (wn >= 2) {
        #pragma unroll
        for (int i = 0; i < 2; i++)
            #pragma unroll
            for (int eh = 0; eh < 2; eh++)
                #pragma unroll
                for (int h = 0; h < 4; h++) {
                    float v = la[i][eh][h];
                    v += __shfl_xor_sync(0xffffffffu, v, 1);
                    v += __shfl_xor_sync(0xffffffffu, v, 2);
                    la[i][eh][h] = v;
                }
        if (tq == 0) {
            #pragma unroll
            for (int i = 0; i < 2; i++)
                #pragma unroll
                for (int eh = 0; eh < 2; eh++) {
                    int m = wm * 32 + i * 16 + gg + eh * 8;
                    #pragma unroll
                    for (int h = 0; h < 4; h++)
                        la_buf[m * 8 + (wn - 2) * 4 + h] = la[i][eh][h];
                }
        }
    }

    // -------- Layer 2: C2[64x128] = h @ W2  (4 k-tiles of 64, single-sync pipeline)
    float acc2[2][4][4];
    #pragma unroll
    for (int i = 0; i < 2; i++)
        #pragma unroll
        for (int j = 0; j < 4; j++)
            #pragma unroll
            for (int e = 0; e < 4; e++) acc2[i][j][e] = 0.f;

    #pragma unroll 1
    for (int kt = 0; kt < 4; kt++) {
        CP_WAIT(0);
        __syncthreads();   // tile kt ready; first iter also publishes h / la_buf writes
        if (kt + 1 < 4) {
            uint32_t base = wbase0 + ((kt + 1) & 1) * WBUFB;
            #pragma unroll
            for (int p = 0; p < 4; p++) {
                int q = tid + p * 256;
                int row = q >> 3, c = q & 7;
                cp16(base + row * W2STRB + c * 16,
                     (const char*)g_w2h + (size_t)row * KTOT * 2 + (kt + 1) * 128 + c * 16);
            }
            CP_COMMIT();
        }
        uint32_t wb = wbase0 + (kt & 1) * WBUFB;
        #pragma unroll
        for (int s = 0; s < 4; s++) {
            uint32_t A0[4], A1[4];
            uint32_t xcol = (uint32_t)(kt * 64 + s * 16 + aColH) * 2;
            ldsm_x4(A0[0], A0[1], A0[2], A0[3],
                    xbase + (wm * 32 + aRow) * (XSTRH * 2) + xcol);
            ldsm_x4(A1[0], A1[1], A1[2], A1[3],
                    xbase + (wm * 32 + 16 + aRow) * (XSTRH * 2) + xcol);
            uint32_t wcol = (uint32_t)(s * 16 + bColH) * 2;
            #pragma unroll
            for (int jj = 0; jj < 2; jj++) {
                uint32_t r0, r1, r2, r3;
                ldsm_x4(r0, r1, r2, r3,
                        wb + (wn * 32 + jj * 16 + bRow) * W2STRB + wcol);
                mma_f16(acc2[0][2*jj],   A0[0], A0[1], A0[2], A0[3], r0, r1);
                mma_f16(acc2[1][2*jj],   A1[0], A1[1], A1[2], A1[3], r0, r1);
                mma_f16(acc2[0][2*jj+1], A0[0], A0[1], A0[2], A0[3], r2, r3);
                mma_f16(acc2[1][2*jj+1], A1[0], A1[1], A1[2], A1[3], r2, r3);
            }
        }
    }

    // -------- epilogue 2: bias, mask, residual, store new_nodes --------
    #pragma unroll
    for (int i = 0; i < 2; i++) {
        #pragma unroll
        for (int j = 0; j < 4; j++) {
            #pragma unroll
            for (int e = 0; e < 4; e += 2) {
                int m = wm * 32 + i * 16 + gg + ((e >> 1) * 8);
                int n = wn * 32 + j * 8 + 2 * tq;
                int nd = n0 + m;
                bool valid = mask_at(mask, b * NN + nd, mode);
                size_t base = ((size_t)b * NN + nd) * OUTN + n;
                float v0 = acc2[i][j][e] + fb2[n];
                float v1 = acc2[i][j][e + 1] + fb2[n + 1];
                out[base]     = (valid ? v0 : 0.f) + nodes[base];
                out[base + 1] = (valid ? v1 : 0.f) + nodes[base + 1];
            }
        }
    }

    // -------- logits: combine the two warp-halves from la_buf --------
    {
        int m = tid >> 2, h = tid & 3;
        float a4 = la_buf[m * 8 + h] + la_buf[m * 8 + 4 + h] + ab2[h];
        int n = n0 + m;
        bool valid = mask_at(mask, b * NN + n, mode);
        g_logits[((size_t)b * NN + n) * NH + h] = valid ? a4 : -INFINITY;
    }
}

// ---------------- softmax stats: one block per batch, float4 over 4 heads ----------
__global__ void nb_softmax_stats_kernel() {
    __shared__ float4 red4[256];
    int b = blockIdx.x;
    int tid = threadIdx.x;
    const float4* lp = (const float4*)(g_logits + (size_t)b * NN * NH);
    float4 mx = make_float4(-INFINITY, -INFINITY, -INFINITY, -INFINITY);
    #pragma unroll 4
    for (int t = 0; t < NN / 256; t++) {
        float4 l = lp[t * 256 + tid];
        mx.x = fmaxf(mx.x, l.x); mx.y = fmaxf(mx.y, l.y);
        mx.z = fmaxf(mx.z, l.z); mx.w = fmaxf(mx.w, l.w);
    }
    red4[tid] = mx;
    __syncthreads();
    for (int o = 128; o; o >>= 1) {
        if (tid < o) {
            float4 a = red4[tid], c = red4[tid + o];
            a.x = fmaxf(a.x, c.x); a.y = fmaxf(a.y, c.y);
            a.z = fmaxf(a.z, c.z); a.w = fmaxf(a.w, c.w);
            red4[tid] = a;
        }
        __syncthreads();
    }
    float4 gm = red4[0];
    __syncthreads();
    float4 sm = make_float4(0.f, 0.f, 0.f, 0.f);
    #pragma unroll 4
    for (int t = 0; t < NN / 256; t++) {
        float4 l = lp[t * 256 + tid];
        sm.x += expf(l.x - gm.x); sm.y += expf(l.y - gm.y);
        sm.z += expf(l.z - gm.z); sm.w += expf(l.w - gm.w);
    }
    red4[tid] = sm;
    __syncthreads();
    for (int o = 128; o; o >>= 1) {
        if (tid < o) {
            float4 a = red4[tid], c = red4[tid + o];
            a.x += c.x; a.y += c.y; a.z += c.z; a.w += c.w;
            red4[tid] = a;
        }
        __syncthreads();
    }
    if (tid < 4) {
        float4 gs = red4[0];
        float gmv = (tid == 0) ? gm.x : (tid == 1) ? gm.y : (tid == 2) ? gm.z : gm.w;
        float gsv = (tid == 0) ? gs.x : (tid == 1) ? gs.y : (tid == 2) ? gs.z : gs.w;
        g_stats[(b * NH + tid) * 2]     = gmv;
        g_stats[(b * NH + tid) * 2 + 1] = gsv;
    }
}

// ---------------- deterministic two-stage pooled reduction (NCH=32, proven) --------
__global__ void nb_pooled_partial_kernel(const float* __restrict__ newnodes) {
    __shared__ float sd[8][OUTN + 4];
    int b  = blockIdx.x;
    int ch = blockIdx.y;
    int q  = threadIdx.x & 31;
    int ro = threadIdx.x >> 5;
    int c4 = q * 4;
    int h  = q >> 3;
    float gmax = g_stats[(b * NH + h) * 2];
    float gsum = g_stats[(b * NH + h) * 2 + 1];
    float scale = 0.08838834764831845f / gsum;   // 1/sqrt(128)/sum
    float ax = 0.f, ay = 0.f, az = 0.f, aw = 0.f;
    int nbase = ch * (NN / NCH);
    #pragma unroll 4
    for (int r = ro; r < NN / NCH; r += 8) {
        int n = nbase + r;
        float l = g_logits[((size_t)b * NN + n) * NH + h];
        float w = expf(l - gmax) * scale;        // masked: l=-inf -> w=0
        float4 v = *(const float4*)&newnodes[((size_t)b * NN + n) * OUTN + c4];
        ax += v.x * w; ay += v.y * w; az += v.z * w; aw += v.w * w;
    }
    sd[ro][c4]     = ax;
    sd[ro][c4 + 1] = ay;
    sd[ro][c4 + 2] = az;
    sd[ro][c4 + 3] = aw;
    __syncthreads();
    if (threadIdx.x < OUTN) {
        float s = 0.f;
        #pragma unroll
        for (int r = 0; r < 8; r++) s += sd[r][threadIdx.x];
        g_part[(ch * BB + b) * OUTN + threadIdx.x] = s;
    }
}

__global__ void nb_pooled_final_kernel(float* __restrict__ out) {
    int idx = blockIdx.x * 256 + threadIdx.x;
    float s = 0.f;
    #pragma unroll
    for (int ch = 0; ch < NCH; ch++) s += g_part[ch * BB * OUTN + idx];
    out[(size_t)BN * OUTN + idx] = s;
}

extern "C" void kernel_launch(void* const* d_in, const int* in_sizes, int n_in,
                              void* d_out, int out_size) {
    const float* nodes        = (const float*)d_in[0];
    const float* pooled_edges = (const float*)d_in[1];
    const void*  mask         = d_in[2];
    const float* globs        = (const float*)d_in[3];
    const float* ctxt         = (const float*)d_in[4];
    const float* ln_g         = (const float*)d_in[5];
    const float* ln_b         = (const float*)d_in[6];
    const float* fw1          = (const float*)d_in[7];
    const float* fb1          = (const float*)d_in[8];
    const float* fw2          = (const float*)d_in[9];
    const float* fb2          = (const float*)d_in[10];
    const float* aw1          = (const float*)d_in[11];
    const float* ab1          = (const float*)d_in[12];
    const float* aw2          = (const float*)d_in[13];
    const float* ab2          = (const float*)d_in[14];
    float* out = (float*)d_out;

    int prep_elems = NTOT * KTOT + OUTN * KTOT + BB * NTOT;
    nb_prep_kernel<<<(prep_elems + 255) / 256, 256>>>(fw1, aw1, fw2, globs, ctxt);

    cudaFuncSetAttribute(nb_main_kernel,
                         cudaFuncAttributeMaxDynamicSharedMemorySize, SMEM_BYTES);
    nb_main_kernel<<<BB * (NN / TM), THREADS, SMEM_BYTES>>>(
        nodes, pooled_edges, mask, ln_g, ln_b,
        fb1, ab1, aw2, ab2, fb2, out);

    nb_softmax_stats_kernel<<<BB, 256>>>();

    dim3 pg(BB, NCH);
    nb_pooled_partial_kernel<<<pg, 256>>>(out);

    nb_pooled_final_kernel<<<(BB * OUTN) / 256, 256>>>(out);
}

// round 14
// speedup vs baseline: 1.1501x; 1.0426x over previous
#include <cuda_runtime.h>
#include <cuda_fp16.h>
#include <math.h>
#include <stdint.h>

#define BB 16
#define NN 4096
#define BN (BB*NN)
#define NIN 128
#define NODE_IN 256
#define HIDF 256
#define HIDA 128
#define OUTN 128
#define NH 4
#define NTOT 384
#define KTOT 256
#define TM 64
#define THREADS 256
#define CPB 64               // CTAs per batch

#define XSTRH 264            // fp16 units; 528B row = 33 x16B (odd) -> LDSM conflict-free
#define W1STRB 80            // L1 weight tile row bytes (64 data + 16 pad; 5 x16B odd)
#define W2STRB 144           // L2 weight tile row bytes (128 data + 16 pad; 9 x16B odd)
#define XBYTES (TM*XSTRH*2)  // 33792
#define WOFF   XBYTES
#define WBUFB  (NTOT*W1STRB) // 30720 per buffer (L2 tile 18432 fits)
#define LAOFF  (WOFF + 2*WBUFB)           // 95232
#define SMEM_BYTES (LAOFF + TM*8*4)       // 97280 -> 2 CTAs/SM

// ---------------- device scratch (no allocation allowed) ----------------
__device__ __half g_w1h[NTOT * KTOT];    // [n][k] plain row-major
__device__ __half g_w2h[OUTN * KTOT];    // [n][k] plain
__device__ float  g_c1[BB * NTOT];       // per-batch context bias (exact fp32)
__device__ float  g_part2[BB * CPB * 2 * OUTN];  // per-CTA, per-wm pooled partials
__device__ float  g_esum[BB * CPB * 8];          // per-CTA, per-wm, per-head exp sums

// ---------------- helpers ----------------
__device__ __forceinline__ uint32_t smem_u32(const void* p) {
    uint32_t a;
    asm("{ .reg .u64 t; cvta.to.shared.u64 t, %1; cvt.u32.u64 %0, t; }" : "=r"(a) : "l"(p));
    return a;
}
__device__ __forceinline__ void cp16(uint32_t dst, const void* src) {
    asm volatile("cp.async.cg.shared.global [%0], [%1], 16;" :: "r"(dst), "l"(src));
}
#define CP_COMMIT() asm volatile("cp.async.commit_group;" ::: "memory")
#define CP_WAIT(n)  asm volatile("cp.async.wait_group %0;" :: "n"(n) : "memory")

__device__ __forceinline__ void ldsm_x4(uint32_t& r0, uint32_t& r1, uint32_t& r2,
                                        uint32_t& r3, uint32_t addr) {
    asm volatile("ldmatrix.sync.aligned.m8n8.x4.shared.b16 {%0,%1,%2,%3}, [%4];"
                 : "=r"(r0), "=r"(r1), "=r"(r2), "=r"(r3) : "r"(addr));
}

__device__ __forceinline__ void mma_f16(float c[4],
                                        unsigned a0, unsigned a1, unsigned a2, unsigned a3,
                                        unsigned b0, unsigned b1) {
    asm volatile(
        "mma.sync.aligned.m16n8k16.row.col.f32.f16.f16.f32 "
        "{%0,%1,%2,%3}, {%4,%5,%6,%7}, {%8,%9}, {%0,%1,%2,%3};\n"
        : "+f"(c[0]), "+f"(c[1]), "+f"(c[2]), "+f"(c[3])
        : "r"(a0), "r"(a1), "r"(a2), "r"(a3), "r"(b0), "r"(b1));
}

__device__ __forceinline__ int mask_mode(const void* mask) {
    unsigned w = *(const unsigned*)mask;      // mask[0,0] is always true (prefix mask)
    if (w == 1u) return 0;                    // int32
    if (w == 0x3f800000u) return 1;           // float32
    return 2;                                 // uint8 / bool
}
__device__ __forceinline__ bool mask_at(const void* mask, int idx, int mode) {
    if (mode == 0) return ((const int*)mask)[idx] != 0;
    if (mode == 1) return ((const float*)mask)[idx] != 0.0f;
    return ((const unsigned char*)mask)[idx] != 0;
}

// ---------------- prep: fp16 weights (plain [n][k]) + context bias ----------------
__global__ void nb_prep_kernel(const float* __restrict__ fw1, const float* __restrict__ aw1,
                               const float* __restrict__ fw2,
                               const float* __restrict__ globs, const float* __restrict__ ctxt) {
    int idx = blockIdx.x * 256 + threadIdx.x;
    if (idx < NTOT * KTOT) {
        int n = idx >> 8, k = idx & 255;
        float v = (n < HIDF) ? fw1[k * HIDF + n] : aw1[k * HIDA + (n - HIDF)];
        g_w1h[idx] = __float2half_rn(v);
    } else if (idx < NTOT * KTOT + OUTN * KTOT) {
        int j = idx - NTOT * KTOT;
        int n = j >> 8, k = j & 255;
        g_w2h[j] = __float2half_rn(fw2[k * OUTN + n]);
    } else if (idx < NTOT * KTOT + OUTN * KTOT + BB * NTOT) {
        int j = idx - (NTOT * KTOT + OUTN * KTOT);
        int b = j / NTOT, n = j - b * NTOT;
        float s = 0.f;
        #pragma unroll 4
        for (int t = 0; t < 128; t++) {
            float hl = (t < 64) ? globs[b * 64 + t] : ctxt[b * 64 + (t - 64)];
            float w  = (n < HIDF) ? fw1[(NODE_IN + t) * HIDF + n]
                                  : aw1[(NODE_IN + t) * HIDA + (n - HIDF)];
            s += hl * w;
        }
        g_c1[j] = s;
    }
}

// ---------------- main fused kernel ----------------
extern __shared__ __align__(16) char smem_raw[];

__global__ void __launch_bounds__(THREADS, 2) nb_main_kernel(
    const float* __restrict__ nodes, const float* __restrict__ pooled_edges,
    const void* __restrict__ mask,
    const float* __restrict__ ln_g, const float* __restrict__ ln_b,
    const float* __restrict__ fb1, const float* __restrict__ ab1,
    const float* __restrict__ aw2, const float* __restrict__ ab2,
    const float* __restrict__ fb2,
    float* __restrict__ out)
{
    __half* xh    = (__half*)smem_raw;                  // [64][264] fp16 plain (h aliases)
    float* la_buf = (float*)(smem_raw + LAOFF);         // [64][8] logits partials

    const int tid  = threadIdx.x;
    const int lane = tid & 31;
    const int wid  = tid >> 5;
    const int b    = blockIdx.x >> 6;          // 64 CTAs per batch
    const int cta  = blockIdx.x & 63;
    const int n0   = cta * TM;

    const int mode = mask_mode(mask);

    // ---- prefix-mask fast path: tile invalid -> new_nodes = nodes, zero partials
    if (!mask_at(mask, b * NN + n0, mode)) {
        const float4* src = (const float4*)(nodes + (size_t)(b * NN + n0) * OUTN);
        float4* dst = (float4*)(out + (size_t)(b * NN + n0) * OUTN);
        #pragma unroll
        for (int p = 0; p < 8; p++)
            dst[tid + p * THREADS] = src[tid + p * THREADS];
        g_part2[((size_t)(b * CPB + cta) * 2) * OUTN + tid] = 0.f;   // covers 2*128
        if (tid < 8) g_esum[(b * CPB + cta) * 8 + tid] = 0.f;
        return;
    }

    const uint32_t xbase  = smem_u32(smem_raw);
    const uint32_t wbase0 = xbase + WOFF;

    // prefetch L1 weight tile 0: 384 rows x 64B = 1536 chunks (6/thread)
    {
        #pragma unroll
        for (int p = 0; p < 6; p++) {
            int q = tid + p * 256;
            int row = q >> 2, c = q & 3;
            cp16(wbase0 + row * W1STRB + c * 16,
                 (const char*)g_w1h + (size_t)row * KTOT * 2 + c * 16);
        }
        CP_COMMIT();
    }

    // -------- Phase 0: LayerNorm -> X (fp16 plain rows), vectorized --------
    for (int m = wid; m < TM; m += 8) {
        const float4* np4 = (const float4*)(nodes + (size_t)(b * NN + n0 + m) * NIN);
        const float4* pp4 = (const float4*)(pooled_edges + (size_t)(b * NN + n0 + m) * NIN);
        float4 va = np4[lane];
        float4 vb = pp4[lane];
        float s  = va.x + va.y + va.z + va.w + vb.x + vb.y + vb.z + vb.w;
        float sq = va.x*va.x + va.y*va.y + va.z*va.z + va.w*va.w
                 + vb.x*vb.x + vb.y*vb.y + vb.z*vb.z + vb.w*vb.w;
        #pragma unroll
        for (int o = 16; o; o >>= 1) {
            s  += __shfl_xor_sync(0xffffffffu, s, o);
            sq += __shfl_xor_sync(0xffffffffu, sq, o);
        }
        float mu  = s * (1.0f / NODE_IN);
        float var = sq * (1.0f / NODE_IN) - mu * mu;
        float rs  = rsqrtf(var + 1e-5f);
        int ja = lane * 4;
        int jb = 128 + lane * 4;
        float a0 = (va.x - mu) * rs * ln_g[ja]     + ln_b[ja];
        float a1 = (va.y - mu) * rs * ln_g[ja + 1] + ln_b[ja + 1];
        float a2 = (va.z - mu) * rs * ln_g[ja + 2] + ln_b[ja + 2];
        float a3 = (va.w - mu) * rs * ln_g[ja + 3] + ln_b[ja + 3];
        float b0 = (vb.x - mu) * rs * ln_g[jb]     + ln_b[jb];
        float b1 = (vb.y - mu) * rs * ln_g[jb + 1] + ln_b[jb + 1];
        float b2 = (vb.z - mu) * rs * ln_g[jb + 2] + ln_b[jb + 2];
        float b3 = (vb.w - mu) * rs * ln_g[jb + 3] + ln_b[jb + 3];
        __half* xr = xh + m * XSTRH;
        *(__half2*)(xr + ja)     = __floats2half2_rn(a0, a1);
        *(__half2*)(xr + ja + 2) = __floats2half2_rn(a2, a3);
        *(__half2*)(xr + jb)     = __floats2half2_rn(b0, b1);
        *(__half2*)(xr + jb + 2) = __floats2half2_rn(b2, b3);
    }

    const int wm = wid >> 2;   // 0..1 (M)
    const int wn = wid & 3;    // 0..3 (N)
    const int tq = lane & 3;
    const int gg = lane >> 2;

    // LDSM address lane-constants
    const int aRow  = (lane & 7) + ((lane >> 3) & 1) * 8;
    const int aColH = ((lane >> 4) & 1) * 8;
    const int bRow  = (lane & 7) + ((lane >> 4) & 1) * 8;
    const int bColH = ((lane >> 3) & 1) * 8;

    // -------- Layer 1: C1[64x384] = X @ W1  (8 k-tiles of 32, single-sync pipeline)
    float acc[2][12][4];
    #pragma unroll
    for (int i = 0; i < 2; i++)
        #pragma unroll
        for (int j = 0; j < 12; j++)
            #pragma unroll
            for (int e = 0; e < 4; e++) acc[i][j][e] = 0.f;

    #pragma unroll 1
    for (int kt = 0; kt < 8; kt++) {
        CP_WAIT(0);
        __syncthreads();
        if (kt + 1 < 8) {
            uint32_t base = wbase0 + ((kt + 1) & 1) * WBUFB;
            #pragma unroll
            for (int p = 0; p < 6; p++) {
                int q = tid + p * 256;
                int row = q >> 2, c = q & 3;
                cp16(base + row * W1STRB + c * 16,
                     (const char*)g_w1h + (size_t)row * KTOT * 2 + (kt + 1) * 64 + c * 16);
            }
            CP_COMMIT();
        }
        uint32_t wb = wbase0 + (kt & 1) * WBUFB;
        #pragma unroll
        for (int s = 0; s < 2; s++) {
            uint32_t A0[4], A1[4];
            uint32_t xcol = (uint32_t)(kt * 32 + s * 16 + aColH) * 2;
            ldsm_x4(A0[0], A0[1], A0[2], A0[3],
                    xbase + (wm * 32 + aRow) * (XSTRH * 2) + xcol);
            ldsm_x4(A1[0], A1[1], A1[2], A1[3],
                    xbase + (wm * 32 + 16 + aRow) * (XSTRH * 2) + xcol);
            uint32_t wcol = (uint32_t)(s * 16 + bColH) * 2;
            #pragma unroll
            for (int jj = 0; jj < 6; jj++) {
                uint32_t r0, r1, r2, r3;
                ldsm_x4(r0, r1, r2, r3,
                        wb + (wn * 96 + jj * 16 + bRow) * W1STRB + wcol);
                mma_f16(acc[0][2*jj],   A0[0], A0[1], A0[2], A0[3], r0, r1);
                mma_f16(acc[1][2*jj],   A1[0], A1[1], A1[2], A1[3], r0, r1);
                mma_f16(acc[0][2*jj+1], A0[0], A0[1], A0[2], A0[3], r2, r3);
                mma_f16(acc[1][2*jj+1], A1[0], A1[1], A1[2], A1[3], r2, r3);
            }
        }
    }
    __syncthreads();   // all L1 reads of X done before epilogue-1 overwrites h into it

    // prefetch L2 weight tile 0 (k-width 64): 128 rows x 128B = 1024 chunks (4/thread)
    {
        #pragma unroll
        for (int p = 0; p < 4; p++) {
            int q = tid + p * 256;
            int row = q >> 3, c = q & 7;
            cp16(wbase0 + row * W2STRB + c * 16,
                 (const char*)g_w2h + (size_t)row * KTOT * 2 + c * 16);
        }
        CP_COMMIT();
    }

    // -------- epilogue 1: bias + ctx + lrelu; feat -> h (fp16 plain); attn -> la ----
    const float* c1b = g_c1 + b * NTOT;
    const float4* aw2v = (const float4*)aw2;
    float la[2][2][4];
    #pragma unroll
    for (int i = 0; i < 2; i++)
        #pragma unroll
        for (int eh = 0; eh < 2; eh++)
            #pragma unroll
            for (int h = 0; h < 4; h++) la[i][eh][h] = 0.f;

    #pragma unroll
    for (int i = 0; i < 2; i++) {
        #pragma unroll
        for (int j = 0; j < 12; j++) {
            int nb = wn * 96 + j * 8 + 2 * tq;
            if (nb < HIDF) {
                #pragma unroll
                for (int eh = 0; eh < 2; eh++) {
                    int m = wm * 32 + i * 16 + gg + eh * 8;
                    float v0 = acc[i][j][eh * 2]     + c1b[nb]     + fb1[nb];
                    float v1 = acc[i][j][eh * 2 + 1] + c1b[nb + 1] + fb1[nb + 1];
                    v0 = (v0 > 0.f) ? v0 : 0.01f * v0;
                    v1 = (v1 > 0.f) ? v1 : 0.01f * v1;
                    *(__half2*)(xh + m * XSTRH + nb) = __floats2half2_rn(v0, v1);
                }
            } else {
                int ka = nb - HIDF;
                float4 w0 = aw2v[ka];
                float4 w1 = aw2v[ka + 1];
                #pragma unroll
                for (int eh = 0; eh < 2; eh++) {
                    float v0 = acc[i][j][eh * 2]     + c1b[nb]     + ab1[ka];
                    float v1 = acc[i][j][eh * 2 + 1] + c1b[nb + 1] + ab1[ka + 1];
                    v0 = (v0 > 0.f) ? v0 : 0.01f * v0;
                    v1 = (v1 > 0.f) ? v1 : 0.01f * v1;
                    la[i][eh][0] += v0 * w0.x + v1 * w1.x;
                    la[i][eh][1] += v0 * w0.y + v1 * w1.y;
                    la[i][eh][2] += v0 * w0.z + v1 * w1.z;
                    la[i][eh][3] += v0 * w0.w + v1 * w1.w;
                }
            }
        }
    }

    // reduce attn partials over the 4 tq lanes, stash in la_buf
    if (wn >= 2) {
        #pragma unroll
        for (int i = 0; i < 2; i++)
            #pragma unroll
            for (int eh = 0; eh < 2; eh++)
                #pragma unroll
                for (int h = 0; h < 4; h++) {
                    float v = la[i][eh][h];
                    v += __shfl_xor_sync(0xffffffffu, v, 1);
                    v += __shfl_xor_sync(0xffffffffu, v, 2);
                    la[i][eh][h] = v;
                }
        if (tq == 0) {
            #pragma unroll
            for (int i = 0; i < 2; i++)
                #pragma unroll
                for (int eh = 0; eh < 2; eh++) {
                    int m = wm * 32 + i * 16 + gg + eh * 8;
                    #pragma unroll
                    for (int h = 0; h < 4; h++)
                        la_buf[m * 8 + (wn - 2) * 4 + h] = la[i][eh][h];
                }
        }
    }

    // -------- Layer 2: C2[64x128] = h @ W2  (4 k-tiles of 64, single-sync pipeline)
    float acc2[2][4][4];
    #pragma unroll
    for (int i = 0; i < 2; i++)
        #pragma unroll
        for (int j = 0; j < 4; j++)
            #pragma unroll
            for (int e = 0; e < 4; e++) acc2[i][j][e] = 0.f;

    #pragma unroll 1
    for (int kt = 0; kt < 4; kt++) {
        CP_WAIT(0);
        __syncthreads();   // first iter also publishes h / la_buf writes
        if (kt + 1 < 4) {
            uint32_t base = wbase0 + ((kt + 1) & 1) * WBUFB;
            #pragma unroll
            for (int p = 0; p < 4; p++) {
                int q = tid + p * 256;
                int row = q >> 3, c = q & 7;
                cp16(base + row * W2STRB + c * 16,
                     (const char*)g_w2h + (size_t)row * KTOT * 2 + (kt + 1) * 128 + c * 16);
            }
            CP_COMMIT();
        }
        uint32_t wb = wbase0 + (kt & 1) * WBUFB;
        #pragma unroll
        for (int s = 0; s < 4; s++) {
            uint32_t A0[4], A1[4];
            uint32_t xcol = (uint32_t)(kt * 64 + s * 16 + aColH) * 2;
            ldsm_x4(A0[0], A0[1], A0[2], A0[3],
                    xbase + (wm * 32 + aRow) * (XSTRH * 2) + xcol);
            ldsm_x4(A1[0], A1[1], A1[2], A1[3],
                    xbase + (wm * 32 + 16 + aRow) * (XSTRH * 2) + xcol);
            uint32_t wcol = (uint32_t)(s * 16 + bColH) * 2;
            #pragma unroll
            for (int jj = 0; jj < 2; jj++) {
                uint32_t r0, r1, r2, r3;
                ldsm_x4(r0, r1, r2, r3,
                        wb + (wn * 32 + jj * 16 + bRow) * W2STRB + wcol);
                mma_f16(acc2[0][2*jj],   A0[0], A0[1], A0[2], A0[3], r0, r1);
                mma_f16(acc2[1][2*jj],   A1[0], A1[1], A1[2], A1[3], r0, r1);
                mma_f16(acc2[0][2*jj+1], A0[0], A0[1], A0[2], A0[3], r2, r3);
                mma_f16(acc2[1][2*jj+1], A1[0], A1[1], A1[2], A1[3], r2, r3);
            }
        }
    }

    // -------- epilogue 2: bias, mask, residual, store; fused pooled partials ------
    // per-m softmax weights (unshifted exp; logits ~N(0,1), fp32-safe), h = wn
    float ew[2][2];
    float esum = 0.f;
    #pragma unroll
    for (int i = 0; i < 2; i++)
        #pragma unroll
        for (int eh = 0; eh < 2; eh++) {
            int m = wm * 32 + i * 16 + gg + eh * 8;
            bool valid = mask_at(mask, b * NN + n0 + m, mode);
            float l = la_buf[m * 8 + wn] + la_buf[m * 8 + 4 + wn] + ab2[wn];
            float e = valid ? expf(l) : 0.f;
            ew[i][eh] = e;
            esum += e;
        }

    float pp[4][2];
    #pragma unroll
    for (int j = 0; j < 4; j++) { pp[j][0] = 0.f; pp[j][1] = 0.f; }

    #pragma unroll
    for (int i = 0; i < 2; i++) {
        #pragma unroll
        for (int j = 0; j < 4; j++) {
            #pragma unroll
            for (int e = 0; e < 4; e += 2) {
                int m = wm * 32 + i * 16 + gg + ((e >> 1) * 8);
                int n = wn * 32 + j * 8 + 2 * tq;
                int nd = n0 + m;
                bool valid = mask_at(mask, b * NN + nd, mode);
                size_t base = ((size_t)b * NN + nd) * OUTN + n;
                float v0 = acc2[i][j][e] + fb2[n];
                float v1 = acc2[i][j][e + 1] + fb2[n + 1];
                float o0 = (valid ? v0 : 0.f) + nodes[base];
                float o1 = (valid ? v1 : 0.f) + nodes[base + 1];
                out[base]     = o0;
                out[base + 1] = o1;
                float w = ew[i][e >> 1];
                pp[j][0] += w * o0;
                pp[j][1] += w * o1;
            }
        }
    }

    // reduce over gg lanes (rows) -> every lane holds full 32-row sums for its channels
    #pragma unroll
    for (int j = 0; j < 4; j++)
        #pragma unroll
        for (int c = 0; c < 2; c++) {
            float v = pp[j][c];
            v += __shfl_xor_sync(0xffffffffu, v, 4);
            v += __shfl_xor_sync(0xffffffffu, v, 8);
            v += __shfl_xor_sync(0xffffffffu, v, 16);
            pp[j][c] = v;
        }
    {
        float v = esum;
        v += __shfl_xor_sync(0xffffffffu, v, 4);
        v += __shfl_xor_sync(0xffffffffu, v, 8);
        v += __shfl_xor_sync(0xffffffffu, v, 16);
        esum = v;
    }

    size_t pbase = ((size_t)(b * CPB + cta) * 2 + wm) * OUTN;
    if (gg == 0) {   // lanes 0..3 (tq 0..3) write their 8 channels
        #pragma unroll
        for (int j = 0; j < 4; j++) {
            int n = wn * 32 + j * 8 + 2 * tq;
            g_part2[pbase + n]     = pp[j][0];
            g_part2[pbase + n + 1] = pp[j][1];
        }
    }
    if (lane == 0)
        g_esum[(b * CPB + cta) * 8 + wm * 4 + wn] = esum;
}

// ---------------- final: combine per-CTA partials, normalize, store pooled --------
__global__ void nb_pooled_final_kernel(float* __restrict__ out) {
    __shared__ float es[NH];
    int b = blockIdx.x;
    int c = threadIdx.x;           // 128 channels
    if (c < NH) {
        float s = 0.f;
        #pragma unroll 4
        for (int cta = 0; cta < CPB; cta++)
            s += g_esum[(b * CPB + cta) * 8 + c] + g_esum[(b * CPB + cta) * 8 + 4 + c];
        es[c] = s;
    }
    __syncthreads();
    float s = 0.f;
    #pragma unroll 4
    for (int cta = 0; cta < CPB; cta++) {
        size_t base = ((size_t)(b * CPB + cta) * 2) * OUTN;
        s += g_part2[base + c] + g_part2[base + OUTN + c];
    }
    out[(size_t)BN * OUTN + b * OUTN + c] = s * 0.08838834764831845f / es[c >> 5];
}

extern "C" void kernel_launch(void* const* d_in, const int* in_sizes, int n_in,
                              void* d_out, int out_size) {
    const float* nodes        = (const float*)d_in[0];
    const float* pooled_edges = (const float*)d_in[1];
    const void*  mask         = d_in[2];
    const float* globs        = (const float*)d_in[3];
    const float* ctxt         = (const float*)d_in[4];
    const float* ln_g         = (const float*)d_in[5];
    const float* ln_b         = (const float*)d_in[6];
    const float* fw1          = (const float*)d_in[7];
    const float* fb1          = (const float*)d_in[8];
    const float* fw2          = (const float*)d_in[9];
    const float* fb2          = (const float*)d_in[10];
    const float* aw1          = (const float*)d_in[11];
    const float* ab1          = (const float*)d_in[12];
    const float* aw2          = (const float*)d_in[13];
    const float* ab2          = (const float*)d_in[14];
    float* out = (float*)d_out;

    int prep_elems = NTOT * KTOT + OUTN * KTOT + BB * NTOT;
    nb_prep_kernel<<<(prep_elems + 255) / 256, 256>>>(fw1, aw1, fw2, globs, ctxt);

    cudaFuncSetAttribute(nb_main_kernel,
                         cudaFuncAttributeMaxDynamicSharedMemorySize, SMEM_BYTES);
    nb_main_kernel<<<BB * (NN / TM), THREADS, SMEM_BYTES>>>(
        nodes, pooled_edges, mask, ln_g, ln_b,
        fb1, ab1, aw2, ab2, fb2, out);

    nb_pooled_final_kernel<<<BB, OUTN>>>(out);
}

// round 15
// speedup vs baseline: 1.2054x; 1.0481x over previous
#include <cuda_runtime.h>
#include <cuda_fp16.h>
#include <math.h>
#include <stdint.h>

#define BB 16
#define NN 4096
#define BN (BB*NN)
#define NIN 128
#define NODE_IN 256
#define HIDF 256
#define HIDA 128
#define OUTN 128
#define NH 4
#define NTOT 384
#define KTOT 256
#define TM 64
#define THREADS 256
#define CPB 64               // CTAs per batch

#define XSTRH 264            // fp16 units; 528B row = 33 x16B (odd) -> LDSM conflict-free
#define W1STRB 80            // L1 weight tile row bytes (64 data + 16 pad; 5 x16B odd)
#define W2STRB 144           // L2 weight tile row bytes (128 data + 16 pad; 9 x16B odd)
#define XBYTES (TM*XSTRH*2)  // 33792
#define WOFF   XBYTES
#define WBUFB  (NTOT*W1STRB) // 30720 per buffer (L2 tile 18432 fits)
#define LAOFF  (WOFF + 2*WBUFB)           // 95232
#define SMEM_BYTES (LAOFF + TM*8*4)       // 97280 -> 2 CTAs/SM

// ---------------- device scratch (no allocation allowed) ----------------
__device__ __half g_w1h[NTOT * KTOT];    // [n][k] plain row-major
__device__ __half g_w2h[OUTN * KTOT];    // [n][k] plain
__device__ float  g_c1[BB * NTOT];       // per-batch context bias (exact fp32)
__device__ float  g_part2[BB * CPB * 2 * OUTN];  // per-CTA, per-wm pooled partials
__device__ float  g_esum[BB * CPB * 8];          // per-CTA, per-wm, per-head exp sums

// ---------------- helpers ----------------
__device__ __forceinline__ uint32_t smem_u32(const void* p) {
    uint32_t a;
    asm("{ .reg .u64 t; cvta.to.shared.u64 t, %1; cvt.u32.u64 %0, t; }" : "=r"(a) : "l"(p));
    return a;
}
__device__ __forceinline__ void cp16(uint32_t dst, const void* src) {
    asm volatile("cp.async.cg.shared.global [%0], [%1], 16;" :: "r"(dst), "l"(src));
}
#define CP_COMMIT() asm volatile("cp.async.commit_group;" ::: "memory")
#define CP_WAIT(n)  asm volatile("cp.async.wait_group %0;" :: "n"(n) : "memory")

__device__ __forceinline__ void ldsm_x4(uint32_t& r0, uint32_t& r1, uint32_t& r2,
                                        uint32_t& r3, uint32_t addr) {
    asm volatile("ldmatrix.sync.aligned.m8n8.x4.shared.b16 {%0,%1,%2,%3}, [%4];"
                 : "=r"(r0), "=r"(r1), "=r"(r2), "=r"(r3) : "r"(addr));
}

__device__ __forceinline__ void mma_f16(float c[4],
                                        unsigned a0, unsigned a1, unsigned a2, unsigned a3,
                                        unsigned b0, unsigned b1) {
    asm volatile(
        "mma.sync.aligned.m16n8k16.row.col.f32.f16.f16.f32 "
        "{%0,%1,%2,%3}, {%4,%5,%6,%7}, {%8,%9}, {%0,%1,%2,%3};\n"
        : "+f"(c[0]), "+f"(c[1]), "+f"(c[2]), "+f"(c[3])
        : "r"(a0), "r"(a1), "r"(a2), "r"(a3), "r"(b0), "r"(b1));
}

__device__ __forceinline__ int mask_mode(const void* mask) {
    unsigned w = *(const unsigned*)mask;      // mask[0,0] is always true (prefix mask)
    if (w == 1u) return 0;                    // int32
    if (w == 0x3f800000u) return 1;           // float32
    return 2;                                 // uint8 / bool
}
__device__ __forceinline__ bool mask_at(const void* mask, int idx, int mode) {
    if (mode == 0) return ((const int*)mask)[idx] != 0;
    if (mode == 1) return ((const float*)mask)[idx] != 0.0f;
    return ((const unsigned char*)mask)[idx] != 0;
}

// ---------------- prep A: weight fp16 transpose, coalesced SOURCE reads ----------
__global__ void nb_prep_w_kernel(const float* __restrict__ fw1,
                                 const float* __restrict__ aw1,
                                 const float* __restrict__ fw2) {
    int idx = blockIdx.x * 256 + threadIdx.x;
    if (idx < KTOT * HIDF) {                       // fw1 [k][256]
        int k = idx >> 8, n = idx & 255;
        g_w1h[n * KTOT + k] = __float2half_rn(fw1[idx]);
    } else if (idx < KTOT * HIDF + KTOT * HIDA) {  // aw1 [k][128]
        int j = idx - KTOT * HIDF;
        int k = j >> 7, n = j & 127;
        g_w1h[(HIDF + n) * KTOT + k] = __float2half_rn(aw1[j]);
    } else if (idx < KTOT * HIDF + KTOT * HIDA + KTOT * OUTN) {  // fw2 [k][128]
        int j = idx - KTOT * HIDF - KTOT * HIDA;
        int k = j >> 7, n = j & 127;
        g_w2h[n * KTOT + k] = __float2half_rn(fw2[j]);
    }
}

// ---------------- prep B: context bias, coalesced row reads ----------------
__global__ void nb_prep_c1_kernel(const float* __restrict__ fw1,
                                  const float* __restrict__ aw1,
                                  const float* __restrict__ globs,
                                  const float* __restrict__ ctxt) {
    __shared__ float hl[128];
    int b = blockIdx.x;
    int n = threadIdx.x;                 // 384 threads, one per output column
    if (n < 128) hl[n] = (n < 64) ? globs[b * 64 + n] : ctxt[b * 64 + (n - 64)];
    __syncthreads();
    float s = 0.f;
    if (n < HIDF) {
        #pragma unroll 8
        for (int t = 0; t < 128; t++)
            s += hl[t] * fw1[(NODE_IN + t) * HIDF + n];
    } else {
        int na = n - HIDF;
        #pragma unroll 8
        for (int t = 0; t < 128; t++)
            s += hl[t] * aw1[(NODE_IN + t) * HIDA + na];
    }
    g_c1[b * NTOT + n] = s;
}

// ---------------- main fused kernel ----------------
extern __shared__ __align__(16) char smem_raw[];

__global__ void __launch_bounds__(THREADS, 2) nb_main_kernel(
    const float* __restrict__ nodes, const float* __restrict__ pooled_edges,
    const void* __restrict__ mask,
    const float* __restrict__ ln_g, const float* __restrict__ ln_b,
    const float* __restrict__ fb1, const float* __restrict__ ab1,
    const float* __restrict__ aw2, const float* __restrict__ ab2,
    const float* __restrict__ fb2,
    float* __restrict__ out)
{
    __half* xh    = (__half*)smem_raw;                  // [64][264] fp16 plain (h aliases)
    float* la_buf = (float*)(smem_raw + LAOFF);         // [64][8] logits partials

    const int tid  = threadIdx.x;
    const int lane = tid & 31;
    const int wid  = tid >> 5;
    const int b    = blockIdx.x >> 6;          // 64 CTAs per batch
    const int cta  = blockIdx.x & 63;
    const int n0   = cta * TM;

    const int mode = mask_mode(mask);

    // ---- prefix-mask fast path: tile invalid -> new_nodes = nodes, zero partials
    if (!mask_at(mask, b * NN + n0, mode)) {
        const float4* src = (const float4*)(nodes + (size_t)(b * NN + n0) * OUTN);
        float4* dst = (float4*)(out + (size_t)(b * NN + n0) * OUTN);
        #pragma unroll
        for (int p = 0; p < 8; p++)
            dst[tid + p * THREADS] = src[tid + p * THREADS];
        g_part2[((size_t)(b * CPB + cta) * 2) * OUTN + tid] = 0.f;   // covers 2*128
        if (tid < 8) g_esum[(b * CPB + cta) * 8 + tid] = 0.f;
        return;
    }

    const uint32_t xbase  = smem_u32(smem_raw);
    const uint32_t wbase0 = xbase + WOFF;

    // prefetch L1 weight tile 0: 384 rows x 64B = 1536 chunks (6/thread)
    {
        #pragma unroll
        for (int p = 0; p < 6; p++) {
            int q = tid + p * 256;
            int row = q >> 2, c = q & 3;
            cp16(wbase0 + row * W1STRB + c * 16,
                 (const char*)g_w1h + (size_t)row * KTOT * 2 + c * 16);
        }
        CP_COMMIT();
    }

    // -------- Phase 0: LayerNorm -> X (fp16 plain rows), vectorized --------
    for (int m = wid; m < TM; m += 8) {
        const float4* np4 = (const float4*)(nodes + (size_t)(b * NN + n0 + m) * NIN);
        const float4* pp4 = (const float4*)(pooled_edges + (size_t)(b * NN + n0 + m) * NIN);
        float4 va = np4[lane];
        float4 vb = pp4[lane];
        float s  = va.x + va.y + va.z + va.w + vb.x + vb.y + vb.z + vb.w;
        float sq = va.x*va.x + va.y*va.y + va.z*va.z + va.w*va.w
                 + vb.x*vb.x + vb.y*vb.y + vb.z*vb.z + vb.w*vb.w;
        #pragma unroll
        for (int o = 16; o; o >>= 1) {
            s  += __shfl_xor_sync(0xffffffffu, s, o);
            sq += __shfl_xor_sync(0xffffffffu, sq, o);
        }
        float mu  = s * (1.0f / NODE_IN);
        float var = sq * (1.0f / NODE_IN) - mu * mu;
        float rs  = rsqrtf(var + 1e-5f);
        int ja = lane * 4;
        int jb = 128 + lane * 4;
        float a0 = (va.x - mu) * rs * ln_g[ja]     + ln_b[ja];
        float a1 = (va.y - mu) * rs * ln_g[ja + 1] + ln_b[ja + 1];
        float a2 = (va.z - mu) * rs * ln_g[ja + 2] + ln_b[ja + 2];
        float a3 = (va.w - mu) * rs * ln_g[ja + 3] + ln_b[ja + 3];
        float b0 = (vb.x - mu) * rs * ln_g[jb]     + ln_b[jb];
        float b1 = (vb.y - mu) * rs * ln_g[jb + 1] + ln_b[jb + 1];
        float b2 = (vb.z - mu) * rs * ln_g[jb + 2] + ln_b[jb + 2];
        float b3 = (vb.w - mu) * rs * ln_g[jb + 3] + ln_b[jb + 3];
        __half* xr = xh + m * XSTRH;
        *(__half2*)(xr + ja)     = __floats2half2_rn(a0, a1);
        *(__half2*)(xr + ja + 2) = __floats2half2_rn(a2, a3);
        *(__half2*)(xr + jb)     = __floats2half2_rn(b0, b1);
        *(__half2*)(xr + jb + 2) = __floats2half2_rn(b2, b3);
    }

    const int wm = wid >> 2;   // 0..1 (M)
    const int wn = wid & 3;    // 0..3 (N)
    const int tq = lane & 3;
    const int gg = lane >> 2;

    // LDSM address lane-constants
    const int aRow  = (lane & 7) + ((lane >> 3) & 1) * 8;
    const int aColH = ((lane >> 4) & 1) * 8;
    const int bRow  = (lane & 7) + ((lane >> 4) & 1) * 8;
    const int bColH = ((lane >> 3) & 1) * 8;

    // -------- Layer 1: C1[64x384] = X @ W1  (8 k-tiles of 32, single-sync pipeline)
    float acc[2][12][4];
    #pragma unroll
    for (int i = 0; i < 2; i++)
        #pragma unroll
        for (int j = 0; j < 12; j++)
            #pragma unroll
            for (int e = 0; e < 4; e++) acc[i][j][e] = 0.f;

    #pragma unroll 1
    for (int kt = 0; kt < 8; kt++) {
        CP_WAIT(0);
        __syncthreads();
        if (kt + 1 < 8) {
            uint32_t base = wbase0 + ((kt + 1) & 1) * WBUFB;
            #pragma unroll
            for (int p = 0; p < 6; p++) {
                int q = tid + p * 256;
                int row = q >> 2, c = q & 3;
                cp16(base + row * W1STRB + c * 16,
                     (const char*)g_w1h + (size_t)row * KTOT * 2 + (kt + 1) * 64 + c * 16);
            }
            CP_COMMIT();
        }
        uint32_t wb = wbase0 + (kt & 1) * WBUFB;
        #pragma unroll
        for (int s = 0; s < 2; s++) {
            uint32_t A0[4], A1[4];
            uint32_t xcol = (uint32_t)(kt * 32 + s * 16 + aColH) * 2;
            ldsm_x4(A0[0], A0[1], A0[2], A0[3],
                    xbase + (wm * 32 + aRow) * (XSTRH * 2) + xcol);
            ldsm_x4(A1[0], A1[1], A1[2], A1[3],
                    xbase + (wm * 32 + 16 + aRow) * (XSTRH * 2) + xcol);
            uint32_t wcol = (uint32_t)(s * 16 + bColH) * 2;
            #pragma unroll
            for (int jj = 0; jj < 6; jj++) {
                uint32_t r0, r1, r2, r3;
                ldsm_x4(r0, r1, r2, r3,
                        wb + (wn * 96 + jj * 16 + bRow) * W1STRB + wcol);
                mma_f16(acc[0][2*jj],   A0[0], A0[1], A0[2], A0[3], r0, r1);
                mma_f16(acc[1][2*jj],   A1[0], A1[1], A1[2], A1[3], r0, r1);
                mma_f16(acc[0][2*jj+1], A0[0], A0[1], A0[2], A0[3], r2, r3);
                mma_f16(acc[1][2*jj+1], A1[0], A1[1], A1[2], A1[3], r2, r3);
            }
        }
    }
    __syncthreads();   // all L1 reads of X done before epilogue-1 overwrites h into it

    // prefetch L2 weight tile 0 (k-width 64): 128 rows x 128B = 1024 chunks (4/thread)
    {
        #pragma unroll
        for (int p = 0; p < 4; p++) {
            int q = tid + p * 256;
            int row = q >> 3, c = q & 7;
            cp16(wbase0 + row * W2STRB + c * 16,
                 (const char*)g_w2h + (size_t)row * KTOT * 2 + c * 16);
        }
        CP_COMMIT();
    }

    // -------- epilogue 1: bias + ctx + lrelu; feat -> h (fp16 plain); attn -> la ----
    const float* c1b = g_c1 + b * NTOT;
    const float4* aw2v = (const float4*)aw2;
    float la[2][2][4];
    #pragma unroll
    for (int i = 0; i < 2; i++)
        #pragma unroll
        for (int eh = 0; eh < 2; eh++)
            #pragma unroll
            for (int h = 0; h < 4; h++) la[i][eh][h] = 0.f;

    #pragma unroll
    for (int i = 0; i < 2; i++) {
        #pragma unroll
        for (int j = 0; j < 12; j++) {
            int nb = wn * 96 + j * 8 + 2 * tq;
            if (nb < HIDF) {
                #pragma unroll
                for (int eh = 0; eh < 2; eh++) {
                    int m = wm * 32 + i * 16 + gg + eh * 8;
                    float v0 = acc[i][j][eh * 2]     + c1b[nb]     + fb1[nb];
                    float v1 = acc[i][j][eh * 2 + 1] + c1b[nb + 1] + fb1[nb + 1];
                    v0 = (v0 > 0.f) ? v0 : 0.01f * v0;
                    v1 = (v1 > 0.f) ? v1 : 0.01f * v1;
                    *(__half2*)(xh + m * XSTRH + nb) = __floats2half2_rn(v0, v1);
                }
            } else {
                int ka = nb - HIDF;
                float4 w0 = aw2v[ka];
                float4 w1 = aw2v[ka + 1];
                #pragma unroll
                for (int eh = 0; eh < 2; eh++) {
                    float v0 = acc[i][j][eh * 2]     + c1b[nb]     + ab1[ka];
                    float v1 = acc[i][j][eh * 2 + 1] + c1b[nb + 1] + ab1[ka + 1];
                    v0 = (v0 > 0.f) ? v0 : 0.01f * v0;
                    v1 = (v1 > 0.f) ? v1 : 0.01f * v1;
                    la[i][eh][0] += v0 * w0.x + v1 * w1.x;
                    la[i][eh][1] += v0 * w0.y + v1 * w1.y;
                    la[i][eh][2] += v0 * w0.z + v1 * w1.z;
                    la[i][eh][3] += v0 * w0.w + v1 * w1.w;
                }
            }
        }
    }

    // reduce attn partials over the 4 tq lanes, stash in la_buf
    if (wn >= 2) {
        #pragma unroll
        for (int i = 0; i < 2; i++)
            #pragma unroll
            for (int eh = 0; eh < 2; eh++)
                #pragma unroll
                for (int h = 0; h < 4; h++) {
                    float v = la[i][eh][h];
                    v += __shfl_xor_sync(0xffffffffu, v, 1);
                    v += __shfl_xor_sync(0xffffffffu, v, 2);
                    la[i][eh][h] = v;
                }
        if (tq == 0) {
            #pragma unroll
            for (int i = 0; i < 2; i++)
                #pragma unroll
                for (int eh = 0; eh < 2; eh++) {
                    int m = wm * 32 + i * 16 + gg + eh * 8;
                    #pragma unroll
                    for (int h = 0; h < 4; h++)
                        la_buf[m * 8 + (wn - 2) * 4 + h] = la[i][eh][h];
                }
        }
    }

    // -------- Layer 2: C2[64x128] = h @ W2  (4 k-tiles of 64, single-sync pipeline)
    float acc2[2][4][4];
    #pragma unroll
    for (int i = 0; i < 2; i++)
        #pragma unroll
        for (int j = 0; j < 4; j++)
            #pragma unroll
            for (int e = 0; e < 4; e++) acc2[i][j][e] = 0.f;

    #pragma unroll 1
    for (int kt = 0; kt < 4; kt++) {
        CP_WAIT(0);
        __syncthreads();   // first iter also publishes h / la_buf writes
        if (kt + 1 < 4) {
            uint32_t base = wbase0 + ((kt + 1) & 1) * WBUFB;
            #pragma unroll
            for (int p = 0; p < 4; p++) {
                int q = tid + p * 256;
                int row = q >> 3, c = q & 7;
                cp16(base + row * W2STRB + c * 16,
                     (const char*)g_w2h + (size_t)row * KTOT * 2 + (kt + 1) * 128 + c * 16);
            }
            CP_COMMIT();
        }
        uint32_t wb = wbase0 + (kt & 1) * WBUFB;
        #pragma unroll
        for (int s = 0; s < 4; s++) {
            uint32_t A0[4], A1[4];
            uint32_t xcol = (uint32_t)(kt * 64 + s * 16 + aColH) * 2;
            ldsm_x4(A0[0], A0[1], A0[2], A0[3],
                    xbase + (wm * 32 + aRow) * (XSTRH * 2) + xcol);
            ldsm_x4(A1[0], A1[1], A1[2], A1[3],
                    xbase + (wm * 32 + 16 + aRow) * (XSTRH * 2) + xcol);
            uint32_t wcol = (uint32_t)(s * 16 + bColH) * 2;
            #pragma unroll
            for (int jj = 0; jj < 2; jj++) {
                uint32_t r0, r1, r2, r3;
                ldsm_x4(r0, r1, r2, r3,
                        wb + (wn * 32 + jj * 16 + bRow) * W2STRB + wcol);
                mma_f16(acc2[0][2*jj],   A0[0], A0[1], A0[2], A0[3], r0, r1);
                mma_f16(acc2[1][2*jj],   A1[0], A1[1], A1[2], A1[3], r0, r1);
                mma_f16(acc2[0][2*jj+1], A0[0], A0[1], A0[2], A0[3], r2, r3);
                mma_f16(acc2[1][2*jj+1], A1[0], A1[1], A1[2], A1[3], r2, r3);
            }
        }
    }

    // -------- epilogue 2: bias, mask, residual, store; fused pooled partials ------
    float ew[2][2];
    float esum = 0.f;
    #pragma unroll
    for (int i = 0; i < 2; i++)
        #pragma unroll
        for (int eh = 0; eh < 2; eh++) {
            int m = wm * 32 + i * 16 + gg + eh * 8;
            bool valid = mask_at(mask, b * NN + n0 + m, mode);
            float l = la_buf[m * 8 + wn] + la_buf[m * 8 + 4 + wn] + ab2[wn];
            float e = valid ? expf(l) : 0.f;
            ew[i][eh] = e;
            esum += e;
        }

    float pp[4][2];
    #pragma unroll
    for (int j = 0; j < 4; j++) { pp[j][0] = 0.f; pp[j][1] = 0.f; }

    #pragma unroll
    for (int i = 0; i < 2; i++) {
        #pragma unroll
        for (int j = 0; j < 4; j++) {
            #pragma unroll
            for (int e = 0; e < 4; e += 2) {
                int m = wm * 32 + i * 16 + gg + ((e >> 1) * 8);
                int n = wn * 32 + j * 8 + 2 * tq;
                int nd = n0 + m;
                bool valid = mask_at(mask, b * NN + nd, mode);
                size_t base = ((size_t)b * NN + nd) * OUTN + n;
                float v0 = acc2[i][j][e] + fb2[n];
                float v1 = acc2[i][j][e + 1] + fb2[n + 1];
                float o0 = (valid ? v0 : 0.f) + nodes[base];
                float o1 = (valid ? v1 : 0.f) + nodes[base + 1];
                out[base]     = o0;
                out[base + 1] = o1;
                float w = ew[i][e >> 1];
                pp[j][0] += w * o0;
                pp[j][1] += w * o1;
            }
        }
    }

    // reduce over gg lanes (rows)
    #pragma unroll
    for (int j = 0; j < 4; j++)
        #pragma unroll
        for (int c = 0; c < 2; c++) {
            float v = pp[j][c];
            v += __shfl_xor_sync(0xffffffffu, v, 4);
            v += __shfl_xor_sync(0xffffffffu, v, 8);
            v += __shfl_xor_sync(0xffffffffu, v, 16);
            pp[j][c] = v;
        }
    {
        float v = esum;
        v += __shfl_xor_sync(0xffffffffu, v, 4);
        v += __shfl_xor_sync(0xffffffffu, v, 8);
        v += __shfl_xor_sync(0xffffffffu, v, 16);
        esum = v;
    }

    size_t pbase = ((size_t)(b * CPB + cta) * 2 + wm) * OUTN;
    if (gg == 0) {
        #pragma unroll
        for (int j = 0; j < 4; j++) {
            int n = wn * 32 + j * 8 + 2 * tq;
            g_part2[pbase + n]     = pp[j][0];
            g_part2[pbase + n + 1] = pp[j][1];
        }
    }
    if (lane == 0)
        g_esum[(b * CPB + cta) * 8 + wm * 4 + wn] = esum;
}

// ---------------- final: combine per-CTA partials, normalize, store pooled --------
__global__ void nb_pooled_final_kernel(float* __restrict__ out) {
    __shared__ float es[NH];
    int b = blockIdx.x;
    int c = threadIdx.x;           // 128 channels
    if (c < NH) {
        float s = 0.f;
        #pragma unroll 4
        for (int cta = 0; cta < CPB; cta++)
            s += g_esum[(b * CPB + cta) * 8 + c] + g_esum[(b * CPB + cta) * 8 + 4 + c];
        es[c] = s;
    }
    __syncthreads();
    float s = 0.f;
    #pragma unroll 4
    for (int cta = 0; cta < CPB; cta++) {
        size_t base = ((size_t)(b * CPB + cta) * 2) * OUTN;
        s += g_part2[base + c] + g_part2[base + OUTN + c];
    }
    out[(size_t)BN * OUTN + b * OUTN + c] = s * 0.08838834764831845f / es[c >> 5];
}

extern "C" void kernel_launch(void* const* d_in, const int* in_sizes, int n_in,
                              void* d_out, int out_size) {
    const float* nodes        = (const float*)d_in[0];
    const float* pooled_edges = (const float*)d_in[1];
    const void*  mask         = d_in[2];
    const float* globs        = (const float*)d_in[3];
    const float* ctxt         = (const float*)d_in[4];
    const float* ln_g         = (const float*)d_in[5];
    const float* ln_b         = (const float*)d_in[6];
    const float* fw1          = (const float*)d_in[7];
    const float* fb1          = (const float*)d_in[8];
    const float* fw2          = (const float*)d_in[9];
    const float* fb2          = (const float*)d_in[10];
    const float* aw1          = (const float*)d_in[11];
    const float* ab1          = (const float*)d_in[12];
    const float* aw2          = (const float*)d_in[13];
    const float* ab2          = (const float*)d_in[14];
    float* out = (float*)d_out;

    int prep_w_elems = KTOT * HIDF + KTOT * HIDA + KTOT * OUTN;   // 131072
    nb_prep_w_kernel<<<prep_w_elems / 256, 256>>>(fw1, aw1, fw2);
    nb_prep_c1_kernel<<<BB, NTOT>>>(fw1, aw1, globs, ctxt);

    cudaFuncSetAttribute(nb_main_kernel,
                         cudaFuncAttributeMaxDynamicSharedMemorySize, SMEM_BYTES);
    nb_main_kernel<<<BB * (NN / TM), THREADS, SMEM_BYTES>>>(
        nodes, pooled_edges, mask, ln_g, ln_b,
        fb1, ab1, aw2, ab2, fb2, out);

    nb_pooled_final_kernel<<<BB, OUTN>>>(out);
}

// round 16
// speedup vs baseline: 1.3071x; 1.0843x over previous
#include <cuda_runtime.h>
#include <cuda_fp16.h>
#include <math.h>
#include <stdint.h>

#define BB 16
#define NN 4096
#define BN (BB*NN)
#define NIN 128
#define NODE_IN 256
#define HIDF 256
#define HIDA 128
#define OUTN 128
#define NH 4
#define NTOT 384
#define KTOT 256
#define TM 64
#define THREADS 256
#define CPB 64               // CTAs per batch

#define XSTRH 264            // fp16 units; 528B row = 33 x16B (odd) -> LDSM conflict-free
#define W1STRB 80            // L1 weight tile row bytes (64 data + 16 pad; 5 x16B odd)
#define W2STRB 144           // L2 weight tile row bytes (128 data + 16 pad; 9 x16B odd)
#define XBYTES (TM*XSTRH*2)  // 33792
#define WOFF   XBYTES
#define WBUFB  (NTOT*W1STRB) // 30720 per buffer (L2 tile 18432 fits)
#define LAOFF  (WOFF + 2*WBUFB)           // 95232
#define SMEM_BYTES (LAOFF + TM*8*4)       // 97280 -> 2 CTAs/SM

// ---------------- device scratch (no allocation allowed) ----------------
__device__ __half g_w1h[NTOT * KTOT];    // [n][k] plain row-major
__device__ __half g_w2h[OUTN * KTOT];    // [n][k] plain
__device__ float  g_c1[BB * NTOT];       // per-batch context bias (exact fp32)
__device__ float  g_part2[BB * CPB * 2 * OUTN];  // per-CTA, per-wm pooled partials
__device__ float  g_esum[BB * CPB * 8];          // per-CTA, per-wm, per-head exp sums

// ---------------- helpers ----------------
__device__ __forceinline__ uint32_t smem_u32(const void* p) {
    uint32_t a;
    asm("{ .reg .u64 t; cvta.to.shared.u64 t, %1; cvt.u32.u64 %0, t; }" : "=r"(a) : "l"(p));
    return a;
}
__device__ __forceinline__ void cp16(uint32_t dst, const void* src) {
    asm volatile("cp.async.cg.shared.global [%0], [%1], 16;" :: "r"(dst), "l"(src));
}
#define CP_COMMIT() asm volatile("cp.async.commit_group;" ::: "memory")
#define CP_WAIT(n)  asm volatile("cp.async.wait_group %0;" :: "n"(n) : "memory")

__device__ __forceinline__ void ldsm_x4(uint32_t& r0, uint32_t& r1, uint32_t& r2,
                                        uint32_t& r3, uint32_t addr) {
    asm volatile("ldmatrix.sync.aligned.m8n8.x4.shared.b16 {%0,%1,%2,%3}, [%4];"
                 : "=r"(r0), "=r"(r1), "=r"(r2), "=r"(r3) : "r"(addr));
}

__device__ __forceinline__ void mma_f16(float c[4],
                                        unsigned a0, unsigned a1, unsigned a2, unsigned a3,
                                        unsigned b0, unsigned b1) {
    asm volatile(
        "mma.sync.aligned.m16n8k16.row.col.f32.f16.f16.f32 "
        "{%0,%1,%2,%3}, {%4,%5,%6,%7}, {%8,%9}, {%0,%1,%2,%3};\n"
        : "+f"(c[0]), "+f"(c[1]), "+f"(c[2]), "+f"(c[3])
        : "r"(a0), "r"(a1), "r"(a2), "r"(a3), "r"(b0), "r"(b1));
}

__device__ __forceinline__ int mask_mode(const void* mask) {
    unsigned w = *(const unsigned*)mask;      // mask[0,0] is always true (prefix mask)
    if (w == 1u) return 0;                    // int32
    if (w == 0x3f800000u) return 1;           // float32
    return 2;                                 // uint8 / bool
}
__device__ __forceinline__ bool mask_at(const void* mask, int idx, int mode) {
    if (mode == 0) return ((const int*)mask)[idx] != 0;
    if (mode == 1) return ((const float*)mask)[idx] != 0.0f;
    return ((const unsigned char*)mask)[idx] != 0;
}

// ---------------- prep A: weight fp16 transpose, coalesced SOURCE reads ----------
__global__ void nb_prep_w_kernel(const float* __restrict__ fw1,
                                 const float* __restrict__ aw1,
                                 const float* __restrict__ fw2) {
    int idx = blockIdx.x * 256 + threadIdx.x;
    if (idx < KTOT * HIDF) {                       // fw1 [k][256]
        int k = idx >> 8, n = idx & 255;
        g_w1h[n * KTOT + k] = __float2half_rn(fw1[idx]);
    } else if (idx < KTOT * HIDF + KTOT * HIDA) {  // aw1 [k][128]
        int j = idx - KTOT * HIDF;
        int k = j >> 7, n = j & 127;
        g_w1h[(HIDF + n) * KTOT + k] = __float2half_rn(aw1[j]);
    } else if (idx < KTOT * HIDF + KTOT * HIDA + KTOT * OUTN) {  // fw2 [k][128]
        int j = idx - KTOT * HIDF - KTOT * HIDA;
        int k = j >> 7, n = j & 127;
        g_w2h[n * KTOT + k] = __float2half_rn(fw2[j]);
    }
}

// ---------------- prep B: context bias, coalesced row reads ----------------
__global__ void nb_prep_c1_kernel(const float* __restrict__ fw1,
                                  const float* __restrict__ aw1,
                                  const float* __restrict__ globs,
                                  const float* __restrict__ ctxt) {
    __shared__ float hl[128];
    int b = blockIdx.x;
    int n = threadIdx.x;                 // 384 threads, one per output column
    if (n < 128) hl[n] = (n < 64) ? globs[b * 64 + n] : ctxt[b * 64 + (n - 64)];
    __syncthreads();
    float s = 0.f;
    if (n < HIDF) {
        #pragma unroll 8
        for (int t = 0; t < 128; t++)
            s += hl[t] * fw1[(NODE_IN + t) * HIDF + n];
    } else {
        int na = n - HIDF;
        #pragma unroll 8
        for (int t = 0; t < 128; t++)
            s += hl[t] * aw1[(NODE_IN + t) * HIDA + na];
    }
    g_c1[b * NTOT + n] = s;
}

// ---------------- main fused kernel ----------------
extern __shared__ __align__(16) char smem_raw[];

__global__ void __launch_bounds__(THREADS, 2) nb_main_kernel(
    const float* __restrict__ nodes, const float* __restrict__ pooled_edges,
    const void* __restrict__ mask,
    const float* __restrict__ ln_g, const float* __restrict__ ln_b,
    const float* __restrict__ fb1, const float* __restrict__ ab1,
    const float* __restrict__ aw2, const float* __restrict__ ab2,
    const float* __restrict__ fb2,
    float* __restrict__ out)
{
    __half* xh    = (__half*)smem_raw;                  // [64][264] fp16 plain (h aliases)
    float* la_buf = (float*)(smem_raw + LAOFF);         // [64][8] logits partials

    const int tid  = threadIdx.x;
    const int lane = tid & 31;
    const int wid  = tid >> 5;
    const int b    = blockIdx.x >> 6;          // 64 CTAs per batch
    const int cta  = blockIdx.x & 63;
    const int n0   = cta * TM;

    const int mode = mask_mode(mask);

    // ---- prefix-mask fast path: tile invalid -> new_nodes = nodes, zero partials
    if (!mask_at(mask, b * NN + n0, mode)) {
        const float4* src = (const float4*)(nodes + (size_t)(b * NN + n0) * OUTN);
        float4* dst = (float4*)(out + (size_t)(b * NN + n0) * OUTN);
        #pragma unroll
        for (int p = 0; p < 8; p++)
            dst[tid + p * THREADS] = src[tid + p * THREADS];
        g_part2[((size_t)(b * CPB + cta) * 2) * OUTN + tid] = 0.f;   // covers 2*128
        if (tid < 8) g_esum[(b * CPB + cta) * 8 + tid] = 0.f;
        return;
    }

    const uint32_t xbase  = smem_u32(smem_raw);
    const uint32_t wbase0 = xbase + WOFF;

    // prefetch L1 weight tile 0: 384 rows x 64B = 1536 chunks (6/thread)
    {
        #pragma unroll
        for (int p = 0; p < 6; p++) {
            int q = tid + p * 256;
            int row = q >> 2, c = q & 3;
            cp16(wbase0 + row * W1STRB + c * 16,
                 (const char*)g_w1h + (size_t)row * KTOT * 2 + c * 16);
        }
        CP_COMMIT();
    }

    // -------- Phase 0: LayerNorm -> X (fp16 plain rows), vectorized --------
    for (int m = wid; m < TM; m += 8) {
        const float4* np4 = (const float4*)(nodes + (size_t)(b * NN + n0 + m) * NIN);
        const float4* pp4 = (const float4*)(pooled_edges + (size_t)(b * NN + n0 + m) * NIN);
        float4 va = np4[lane];
        float4 vb = pp4[lane];
        float s  = va.x + va.y + va.z + va.w + vb.x + vb.y + vb.z + vb.w;
        float sq = va.x*va.x + va.y*va.y + va.z*va.z + va.w*va.w
                 + vb.x*vb.x + vb.y*vb.y + vb.z*vb.z + vb.w*vb.w;
        #pragma unroll
        for (int o = 16; o; o >>= 1) {
            s  += __shfl_xor_sync(0xffffffffu, s, o);
            sq += __shfl_xor_sync(0xffffffffu, sq, o);
        }
        float mu  = s * (1.0f / NODE_IN);
        float var = sq * (1.0f / NODE_IN) - mu * mu;
        float rs  = rsqrtf(var + 1e-5f);
        int ja = lane * 4;
        int jb = 128 + lane * 4;
        float a0 = (va.x - mu) * rs * ln_g[ja]     + ln_b[ja];
        float a1 = (va.y - mu) * rs * ln_g[ja + 1] + ln_b[ja + 1];
        float a2 = (va.z - mu) * rs * ln_g[ja + 2] + ln_b[ja + 2];
        float a3 = (va.w - mu) * rs * ln_g[ja + 3] + ln_b[ja + 3];
        float b0 = (vb.x - mu) * rs * ln_g[jb]     + ln_b[jb];
        float b1 = (vb.y - mu) * rs * ln_g[jb + 1] + ln_b[jb + 1];
        float b2 = (vb.z - mu) * rs * ln_g[jb + 2] + ln_b[jb + 2];
        float b3 = (vb.w - mu) * rs * ln_g[jb + 3] + ln_b[jb + 3];
        __half* xr = xh + m * XSTRH;
        *(__half2*)(xr + ja)     = __floats2half2_rn(a0, a1);
        *(__half2*)(xr + ja + 2) = __floats2half2_rn(a2, a3);
        *(__half2*)(xr + jb)     = __floats2half2_rn(b0, b1);
        *(__half2*)(xr + jb + 2) = __floats2half2_rn(b2, b3);
    }

    const int wm = wid >> 2;   // 0..1 (M)
    const int wn = wid & 3;    // 0..3 (N)
    const int tq = lane & 3;
    const int gg = lane >> 2;

    // LDSM address lane-constants
    const int aRow  = (lane & 7) + ((lane >> 3) & 1) * 8;
    const int aColH = ((lane >> 4) & 1) * 8;
    const int bRow  = (lane & 7) + ((lane >> 4) & 1) * 8;
    const int bColH = ((lane >> 3) & 1) * 8;

    // -------- Layer 1: C1[64x384] = X @ W1  (8 k-tiles of 32, single-sync pipeline)
    float acc[2][12][4];
    #pragma unroll
    for (int i = 0; i < 2; i++)
        #pragma unroll
        for (int j = 0; j < 12; j++)
            #pragma unroll
            for (int e = 0; e < 4; e++) acc[i][j][e] = 0.f;

    #pragma unroll 1
    for (int kt = 0; kt < 8; kt++) {
        CP_WAIT(0);
        __syncthreads();
        if (kt + 1 < 8) {
            uint32_t base = wbase0 + ((kt + 1) & 1) * WBUFB;
            #pragma unroll
            for (int p = 0; p < 6; p++) {
                int q = tid + p * 256;
                int row = q >> 2, c = q & 3;
                cp16(base + row * W1STRB + c * 16,
                     (const char*)g_w1h + (size_t)row * KTOT * 2 + (kt + 1) * 64 + c * 16);
            }
            CP_COMMIT();
        }
        uint32_t wb = wbase0 + (kt & 1) * WBUFB;
        #pragma unroll
        for (int s = 0; s < 2; s++) {
            uint32_t A0[4], A1[4];
            uint32_t xcol = (uint32_t)(kt * 32 + s * 16 + aColH) * 2;
            ldsm_x4(A0[0], A0[1], A0[2], A0[3],
                    xbase + (wm * 32 + aRow) * (XSTRH * 2) + xcol);
            ldsm_x4(A1[0], A1[1], A1[2], A1[3],
                    xbase + (wm * 32 + 16 + aRow) * (XSTRH * 2) + xcol);
            uint32_t wcol = (uint32_t)(s * 16 + bColH) * 2;
            #pragma unroll
            for (int jj = 0; jj < 6; jj++) {
                uint32_t r0, r1, r2, r3;
                ldsm_x4(r0, r1, r2, r3,
                        wb + (wn * 96 + jj * 16 + bRow) * W1STRB + wcol);
                mma_f16(acc[0][2*jj],   A0[0], A0[1], A0[2], A0[3], r0, r1);
                mma_f16(acc[1][2*jj],   A1[0], A1[1], A1[2], A1[3], r0, r1);
                mma_f16(acc[0][2*jj+1], A0[0], A0[1], A0[2], A0[3], r2, r3);
                mma_f16(acc[1][2*jj+1], A1[0], A1[1], A1[2], A1[3], r2, r3);
            }
        }
    }
    __syncthreads();   // all L1 reads of X done before epilogue-1 overwrites h into it

    // prefetch L2 weight tile 0 (k-width 64): 128 rows x 128B = 1024 chunks (4/thread)
    {
        #pragma unroll
        for (int p = 0; p < 4; p++) {
            int q = tid + p * 256;
            int row = q >> 3, c = q & 7;
            cp16(wbase0 + row * W2STRB + c * 16,
                 (const char*)g_w2h + (size_t)row * KTOT * 2 + c * 16);
        }
        CP_COMMIT();
    }

    // -------- epilogue 1: bias + ctx + lrelu; feat -> h (fp16 plain); attn -> la ----
    const float* c1b = g_c1 + b * NTOT;
    const float4* aw2v = (const float4*)aw2;
    float la[2][2][4];
    #pragma unroll
    for (int i = 0; i < 2; i++)
        #pragma unroll
        for (int eh = 0; eh < 2; eh++)
            #pragma unroll
            for (int h = 0; h < 4; h++) la[i][eh][h] = 0.f;

    #pragma unroll
    for (int i = 0; i < 2; i++) {
        #pragma unroll
        for (int j = 0; j < 12; j++) {
            int nb = wn * 96 + j * 8 + 2 * tq;
            if (nb < HIDF) {
                #pragma unroll
                for (int eh = 0; eh < 2; eh++) {
                    int m = wm * 32 + i * 16 + gg + eh * 8;
                    float v0 = acc[i][j][eh * 2]     + c1b[nb]     + fb1[nb];
                    float v1 = acc[i][j][eh * 2 + 1] + c1b[nb + 1] + fb1[nb + 1];
                    v0 = (v0 > 0.f) ? v0 : 0.01f * v0;
                    v1 = (v1 > 0.f) ? v1 : 0.01f * v1;
                    *(__half2*)(xh + m * XSTRH + nb) = __floats2half2_rn(v0, v1);
                }
            } else {
                int ka = nb - HIDF;
                float4 w0 = aw2v[ka];
                float4 w1 = aw2v[ka + 1];
                #pragma unroll
                for (int eh = 0; eh < 2; eh++) {
                    float v0 = acc[i][j][eh * 2]     + c1b[nb]     + ab1[ka];
                    float v1 = acc[i][j][eh * 2 + 1] + c1b[nb + 1] + ab1[ka + 1];
                    v0 = (v0 > 0.f) ? v0 : 0.01f * v0;
                    v1 = (v1 > 0.f) ? v1 : 0.01f * v1;
                    la[i][eh][0] += v0 * w0.x + v1 * w1.x;
                    la[i][eh][1] += v0 * w0.y + v1 * w1.y;
                    la[i][eh][2] += v0 * w0.z + v1 * w1.z;
                    la[i][eh][3] += v0 * w0.w + v1 * w1.w;
                }
            }
        }
    }

    // reduce attn partials over the 4 tq lanes, stash in la_buf
    if (wn >= 2) {
        #pragma unroll
        for (int i = 0; i < 2; i++)
            #pragma unroll
            for (int eh = 0; eh < 2; eh++)
                #pragma unroll
                for (int h = 0; h < 4; h++) {
                    float v = la[i][eh][h];
                    v += __shfl_xor_sync(0xffffffffu, v, 1);
                    v += __shfl_xor_sync(0xffffffffu, v, 2);
                    la[i][eh][h] = v;
                }
        if (tq == 0) {
            #pragma unroll
            for (int i = 0; i < 2; i++)
                #pragma unroll
                for (int eh = 0; eh < 2; eh++) {
                    int m = wm * 32 + i * 16 + gg + eh * 8;
                    #pragma unroll
                    for (int h = 0; h < 4; h++)
                        la_buf[m * 8 + (wn - 2) * 4 + h] = la[i][eh][h];
                }
        }
    }

    // -------- Layer 2: C2[64x128] = h @ W2  (4 k-tiles of 64, single-sync pipeline)
    float acc2[2][4][4];
    #pragma unroll
    for (int i = 0; i < 2; i++)
        #pragma unroll
        for (int j = 0; j < 4; j++)
            #pragma unroll
            for (int e = 0; e < 4; e++) acc2[i][j][e] = 0.f;

    #pragma unroll 1
    for (int kt = 0; kt < 4; kt++) {
        CP_WAIT(0);
        __syncthreads();   // first iter also publishes h / la_buf writes
        if (kt + 1 < 4) {
            uint32_t base = wbase0 + ((kt + 1) & 1) * WBUFB;
            #pragma unroll
            for (int p = 0; p < 4; p++) {
                int q = tid + p * 256;
                int row = q >> 3, c = q & 7;
                cp16(base + row * W2STRB + c * 16,
                     (const char*)g_w2h + (size_t)row * KTOT * 2 + (kt + 1) * 128 + c * 16);
            }
            CP_COMMIT();
        }
        uint32_t wb = wbase0 + (kt & 1) * WBUFB;
        #pragma unroll
        for (int s = 0; s < 4; s++) {
            uint32_t A0[4], A1[4];
            uint32_t xcol = (uint32_t)(kt * 64 + s * 16 + aColH) * 2;
            ldsm_x4(A0[0], A0[1], A0[2], A0[3],
                    xbase + (wm * 32 + aRow) * (XSTRH * 2) + xcol);
            ldsm_x4(A1[0], A1[1], A1[2], A1[3],
                    xbase + (wm * 32 + 16 + aRow) * (XSTRH * 2) + xcol);
            uint32_t wcol = (uint32_t)(s * 16 + bColH) * 2;
            #pragma unroll
            for (int jj = 0; jj < 2; jj++) {
                uint32_t r0, r1, r2, r3;
                ldsm_x4(r0, r1, r2, r3,
                        wb + (wn * 32 + jj * 16 + bRow) * W2STRB + wcol);
                mma_f16(acc2[0][2*jj],   A0[0], A0[1], A0[2], A0[3], r0, r1);
                mma_f16(acc2[1][2*jj],   A1[0], A1[1], A1[2], A1[3], r0, r1);
                mma_f16(acc2[0][2*jj+1], A0[0], A0[1], A0[2], A0[3], r2, r3);
                mma_f16(acc2[1][2*jj+1], A1[0], A1[1], A1[2], A1[3], r2, r3);
            }
        }
    }

    // -------- epilogue 2: bias, mask, residual, store; fused pooled partials ------
    float ew[2][2];
    float esum = 0.f;
    #pragma unroll
    for (int i = 0; i < 2; i++)
        #pragma unroll
        for (int eh = 0; eh < 2; eh++) {
            int m = wm * 32 + i * 16 + gg + eh * 8;
            bool valid = mask_at(mask, b * NN + n0 + m, mode);
            float l = la_buf[m * 8 + wn] + la_buf[m * 8 + 4 + wn] + ab2[wn];
            float e = valid ? expf(l) : 0.f;
            ew[i][eh] = e;
            esum += e;
        }

    float pp[4][2];
    #pragma unroll
    for (int j = 0; j < 4; j++) { pp[j][0] = 0.f; pp[j][1] = 0.f; }

    #pragma unroll
    for (int i = 0; i < 2; i++) {
        #pragma unroll
        for (int j = 0; j < 4; j++) {
            #pragma unroll
            for (int e = 0; e < 4; e += 2) {
                int m = wm * 32 + i * 16 + gg + ((e >> 1) * 8);
                int n = wn * 32 + j * 8 + 2 * tq;
                int nd = n0 + m;
                bool valid = mask_at(mask, b * NN + nd, mode);
                size_t base = ((size_t)b * NN + nd) * OUTN + n;
                float v0 = acc2[i][j][e] + fb2[n];
                float v1 = acc2[i][j][e + 1] + fb2[n + 1];
                float o0 = (valid ? v0 : 0.f) + nodes[base];
                float o1 = (valid ? v1 : 0.f) + nodes[base + 1];
                out[base]     = o0;
                out[base + 1] = o1;
                float w = ew[i][e >> 1];
                pp[j][0] += w * o0;
                pp[j][1] += w * o1;
            }
        }
    }

    // reduce over gg lanes (rows)
    #pragma unroll
    for (int j = 0; j < 4; j++)
        #pragma unroll
        for (int c = 0; c < 2; c++) {
            float v = pp[j][c];
            v += __shfl_xor_sync(0xffffffffu, v, 4);
            v += __shfl_xor_sync(0xffffffffu, v, 8);
            v += __shfl_xor_sync(0xffffffffu, v, 16);
            pp[j][c] = v;
        }
    {
        float v = esum;
        v += __shfl_xor_sync(0xffffffffu, v, 4);
        v += __shfl_xor_sync(0xffffffffu, v, 8);
        v += __shfl_xor_sync(0xffffffffu, v, 16);
        esum = v;
    }

    size_t pbase = ((size_t)(b * CPB + cta) * 2 + wm) * OUTN;
    if (gg == 0) {
        #pragma unroll
        for (int j = 0; j < 4; j++) {
            int n = wn * 32 + j * 8 + 2 * tq;
            g_part2[pbase + n]     = pp[j][0];
            g_part2[pbase + n + 1] = pp[j][1];
        }
    }
    if (lane == 0)
        g_esum[(b * CPB + cta) * 8 + wm * 4 + wn] = esum;
}

// ---------------- final: parallel combine of per-CTA partials, normalize ----------
__global__ void nb_pooled_final_kernel(float* __restrict__ out) {
    __shared__ float esr[512];
    __shared__ float ps[4][OUTN];
    int b   = blockIdx.x;
    int tid = threadIdx.x;               // 512 threads

    // esum tree-reduction: layout idx = cta*8 + wm*4 + head, head = idx & 3;
    // all strides are multiples of 4, so esr[0..3] end as exact per-head sums
    esr[tid] = g_esum[b * CPB * 8 + tid];   // CPB*8 = 512
    __syncthreads();
    #pragma unroll
    for (int o = 256; o >= 4; o >>= 1) {
        if (tid < o) esr[tid] += esr[tid + o];
        __syncthreads();
    }

    // pooled partials: channel c, slice s of 16 CTAs (coalesced, unrolled -> high MLP)
    int c = tid & 127, s = tid >> 7;
    float acc = 0.f;
    #pragma unroll
    for (int q = 0; q < 16; q++) {
        int cta = s * 16 + q;
        size_t base = ((size_t)(b * CPB + cta) * 2) * OUTN;
        acc += g_part2[base + c] + g_part2[base + OUTN + c];
    }
    ps[s][c] = acc;
    __syncthreads();
    if (tid < OUTN) {
        float v = ps[0][tid] + ps[1][tid] + ps[2][tid] + ps[3][tid];
        out[(size_t)BN * OUTN + b * OUTN + tid] =
            v * 0.08838834764831845f / esr[tid >> 5];
    }
}

extern "C" void kernel_launch(void* const* d_in, const int* in_sizes, int n_in,
                              void* d_out, int out_size) {
    const float* nodes        = (const float*)d_in[0];
    const float* pooled_edges = (const float*)d_in[1];
    const void*  mask         = d_in[2];
    const float* globs        = (const float*)d_in[3];
    const float* ctxt         = (const float*)d_in[4];
    const float* ln_g         = (const float*)d_in[5];
    const float* ln_b         = (const float*)d_in[6];
    const float* fw1          = (const float*)d_in[7];
    const float* fb1          = (const float*)d_in[8];
    const float* fw2          = (const float*)d_in[9];
    const float* fb2          = (const float*)d_in[10];
    const float* aw1          = (const float*)d_in[11];
    const float* ab1          = (const float*)d_in[12];
    const float* aw2          = (const float*)d_in[13];
    const float* ab2          = (const float*)d_in[14];
    float* out = (float*)d_out;

    int prep_w_elems = KTOT * HIDF + KTOT * HIDA + KTOT * OUTN;   // 131072
    nb_prep_w_kernel<<<prep_w_elems / 256, 256>>>(fw1, aw1, fw2);
    nb_prep_c1_kernel<<<BB, NTOT>>>(fw1, aw1, globs, ctxt);

    cudaFuncSetAttribute(nb_main_kernel,
                         cudaFuncAttributeMaxDynamicSharedMemorySize, SMEM_BYTES);
    nb_main_kernel<<<BB * (NN / TM), THREADS, SMEM_BYTES>>>(
        nodes, pooled_edges, mask, ln_g, ln_b,
        fb1, ab1, aw2, ab2, fb2, out);

    nb_pooled_final_kernel<<<BB, 512>>>(out);
}